// round 14
// baseline (speedup 1.0000x reference)
#include <cuda_runtime.h>
#include <cuda_fp16.h>
#include <math.h>
#include <stdint.h>

#define S_    4
#define N_    10000
#define NP_   10048
#define L_    8
#define F_    128
#define G3_   384
#define OR_   64
#define SUB_  100
#define SEQ_  (S_*N_)
#define MB_   64
#define NT_   256
#define TILES_ (SEQ_/MB_)          // 625
#define PTILES_ (NP_/MB_)          // 157
#define NB_LOSS (S_*SUB_*(L_-1))
#define LOSS_CNT 179200.0f
#define HP_   136                  // fp16 tile pitch

__device__ int      g_walksf[SEQ_*L_];
__device__ unsigned g_upk[SEQ_];
__device__ float    g_wg[8*G3_];
__device__ float    g_P[N_*G3_];
__device__ __half   g_hH[(size_t)NP_*F_];
__device__ __half   g_ywH[(size_t)L_*SEQ_*F_];
__device__ float    g_hf[(size_t)SEQ_*F_];            // fp32 recurrent state (L2-resident)
__device__ unsigned char g_need[SEQ_];
__device__ float    g_yseq[L_-1][SEQ_*F_];
__device__ float    g_part1[NB_LOSS];
__device__ float    g_part2[NB_LOSS];
__device__ float    g_posw;
__device__ __half   g_W1[G3_*F_];
__device__ __half   g_W2[G3_*F_];
__device__ __half   g_WX[G3_*F_];
__device__ __half   g_WA[G3_*F_];

__device__ __forceinline__ float sigf(float x) { return __fdividef(1.f, 1.f + __expf(-x)); }
__device__ __forceinline__ float tanh_s(float x) {
    float ax = fabsf(x); float e = __expf(-2.f*ax);
    return copysignf(__fdividef(1.f - e, 1.f + e), x);
}
__device__ __forceinline__ float softplusf(float x) {
    return fmaxf(x, 0.f) + log1pf(__expf(-fabsf(x)));
}

__device__ __forceinline__ void mma_f16(float c[4], uint32_t a0, uint32_t a1,
                                        uint32_t a2, uint32_t a3, uint32_t b0, uint32_t b1) {
    asm volatile("mma.sync.aligned.m16n8k16.row.col.f32.f16.f16.f32 "
                 "{%0,%1,%2,%3}, {%4,%5,%6,%7}, {%8,%9}, {%0,%1,%2,%3};\n"
                 : "+f"(c[0]), "+f"(c[1]), "+f"(c[2]), "+f"(c[3])
                 : "r"(a0), "r"(a1), "r"(a2), "r"(a3), "r"(b0), "r"(b1));
}
__device__ __forceinline__ void ldsm_x4(uint32_t& r0, uint32_t& r1, uint32_t& r2, uint32_t& r3,
                                        const void* p) {
    uint32_t a = (uint32_t)__cvta_generic_to_shared(p);
    asm volatile("ldmatrix.sync.aligned.m8n8.x4.shared.b16 {%0,%1,%2,%3}, [%4];"
                 : "=r"(r0), "=r"(r1), "=r"(r2), "=r"(r3) : "r"(a));
}

// fp16 single-pass GEMM: acc[2][4][4] += A(32x128, pitch HP_) @ W^T (128x128, pitch HP_)
__device__ __forceinline__ void run_f16(float (&acc)[2][4][4],
    const __half* __restrict__ A, const __half* __restrict__ W, int lane, int wc)
{
    const int rl = lane & 15;
    const int kp = (lane >> 4) << 3;
#pragma unroll
    for (int ks = 0; ks < 8; ks++) {
        const int k0 = ks*16 + kp;
        uint32_t a[2][4];
#pragma unroll
        for (int mt = 0; mt < 2; mt++)
            ldsm_x4(a[mt][0], a[mt][1], a[mt][2], a[mt][3], A + (mt*16 + rl)*HP_ + k0);
#pragma unroll
        for (int np = 0; np < 2; np++) {
            uint32_t b[4];
            ldsm_x4(b[0], b[1], b[2], b[3], W + (wc*32 + np*16 + rl)*HP_ + k0);
#pragma unroll
            for (int mt = 0; mt < 2; mt++) {
                mma_f16(acc[mt][np*2+0], a[mt][0], a[mt][1], a[mt][2], a[mt][3], b[0], b[2]);
                mma_f16(acc[mt][np*2+1], a[mt][0], a[mt][1], a[mt][2], a[mt][3], b[1], b[3]);
            }
        }
    }
}

__device__ __forceinline__ void cpa16(uint32_t d, const void* s) {
    asm volatile("cp.async.cg.shared.global [%0], [%1], 16;\n" :: "r"(d), "l"(s));
}
__device__ __forceinline__ void stage1(uint32_t dstB, const __half* __restrict__ src, int tid)
{
#pragma unroll
    for (int it = 0; it < 8; it++) {
        int i = tid + it*NT_;
        int row = i >> 4, seg = (i & 15) << 3;
        cpa16(dstB + (uint32_t)(row*HP_ + seg)*2u, src + row*128 + seg);
    }
}
__device__ __forceinline__ void cp_wait_all() {
    asm volatile("cp.async.commit_group;\n");
    asm volatile("cp.async.wait_group 0;\n" ::: "memory");
}
// pipeline phase: stage NEXT chunk into the other buffer, guarantee CURRENT chunk landed
__device__ __forceinline__ void phaseP(uint32_t nbuf, const __half* __restrict__ nsrc, int tid)
{
    __syncthreads();                    // prior run on nbuf finished
    stage1(nbuf, nsrc, tid);
    asm volatile("cp.async.commit_group;\n");
    asm volatile("cp.async.wait_group 1;\n" ::: "memory");   // chunk staged last phase landed
    __syncthreads();
}

// gi loaders
__device__ __forceinline__ void load_gi1(float (&acc)[2][4][4], int jg, int t,
    const int* __restrict__ sh_i, const float* __restrict__ sh_bh, int addbias,
    int rbase, int g, int tg2, int wc)
{
#pragma unroll
    for (int mt = 0; mt < 2; mt++) {
        int u0 = (sh_i[rbase + mt*16 + g]     >> (4*t)) & 7;
        int u1 = (sh_i[rbase + mt*16 + g + 8] >> (4*t)) & 7;
#pragma unroll
        for (int nt = 0; nt < 4; nt++) {
            int cc = jg*F_ + wc*32 + nt*8 + tg2;
            float2 p0 = *(const float2*)&g_wg[u0*G3_ + cc];
            float2 p1 = *(const float2*)&g_wg[u1*G3_ + cc];
            acc[mt][nt][0]=p0.x; acc[mt][nt][1]=p0.y; acc[mt][nt][2]=p1.x; acc[mt][nt][3]=p1.y;
            if (addbias) {
                float2 bh = *(const float2*)&sh_bh[cc];
                acc[mt][nt][0]+=bh.x; acc[mt][nt][1]+=bh.y; acc[mt][nt][2]+=bh.x; acc[mt][nt][3]+=bh.y;
            }
        }
    }
}
__device__ __forceinline__ void load_gi2(float (&acc)[2][4][4], int jg,
    const int* __restrict__ sh_i, const float* __restrict__ sh_bh, int addbias,
    int rbase, int g, int tg2, int wc)
{
#pragma unroll
    for (int mt = 0; mt < 2; mt++) {
        int i0 = sh_i[rbase + mt*16 + g], i1 = sh_i[rbase + mt*16 + g + 8];
#pragma unroll
        for (int nt = 0; nt < 4; nt++) {
            int cc = jg*F_ + wc*32 + nt*8 + tg2;
            float2 p0 = *(const float2*)&g_P[(size_t)i0*G3_ + cc];
            float2 p1 = *(const float2*)&g_P[(size_t)i1*G3_ + cc];
            acc[mt][nt][0]=p0.x; acc[mt][nt][1]=p0.y; acc[mt][nt][2]=p1.x; acc[mt][nt][3]=p1.y;
            if (addbias) {
                float2 bh = *(const float2*)&sh_bh[cc];
                acc[mt][nt][0]+=bh.x; acc[mt][nt][1]+=bh.y; acc[mt][nt][2]+=bh.x; acc[mt][nt][3]+=bh.y;
            }
        }
    }
}

// ---------------- preprocessing ----------------
__global__ void prep_kernel(const int* __restrict__ walks)
{
    int m = blockIdx.x * blockDim.x + threadIdx.x;
    if (m >= SEQ_) return;
    int w[L_];
#pragma unroll
    for (int p = 0; p < L_; p++) w[p] = walks[m*L_ + p];
    unsigned pk = 0;
#pragma unroll
    for (int t = 0; t < L_; t++) {
        int p = L_-1-t, wp = w[p], u = p;
#pragma unroll
        for (int q = L_-1; q >= 0; q--) if (w[q] == wp) u = q;
        g_walksf[m*L_ + t] = wp;
        pk |= ((unsigned)u) << (4*t);
    }
    g_upk[m] = pk;
    g_need[m] = 0;
}

__global__ void flag_kernel(const int* __restrict__ idxs)
{
    int i = threadIdx.x + blockIdx.x*128;
    if (i >= S_*SUB_) return;
    int s = i / SUB_, j = i % SUB_;
    g_need[s*N_ + idxs[j]] = 1;
}

__global__ void wg_kernel(const float* __restrict__ Wih_w, const float* __restrict__ bih_w)
{
    int j = threadIdx.x;
    float b = bih_w[j];
#pragma unroll
    for (int u = 0; u < 8; u++) g_wg[u*G3_ + j] = Wih_w[j*8 + u] + b;
}

__global__ void pack_kernel(const float* __restrict__ Whh_w, const float* __restrict__ Whh,
                            const float* __restrict__ Wih)
{
    int i = blockIdx.x * 256 + threadIdx.x;
    if (i >= G3_*F_) return;
    g_W1[i] = __float2half(Whh_w[i]);
    g_W2[i] = __float2half(Whh[i]);
    int n = i >> 7, k = i & 127;
    g_WX[i] = __float2half(Wih[n*256 + 128 + k]);
    g_WA[i] = __float2half(Wih[n*256 + k]);
}

__global__ void packh_kernel(const float* __restrict__ h)
{
    int i = blockIdx.x * 256 + threadIdx.x;
    if (i >= NP_*F_) return;
    int n = i >> 7, k = i & 127;
    float v = (n < N_) ? h[(size_t)n*F_ + k] : 0.f;
    g_hH[(size_t)n*F_ + k] = __float2half(v);
}

// ---------------- P = h @ WihA^T + bih (fp16 tensor cores) ----------------
__global__ void __launch_bounds__(NT_) pT_kernel(const float* __restrict__ bih)
{
    extern __shared__ char smc[];
    __half* sh_x = (__half*)smc;                  // 17408
    __half* sh_W = (__half*)(smc + 17408);        // 34816

    const int tid = threadIdx.x, wid = tid >> 5, lane = tid & 31;
    const int wr = wid & 1, wc = wid >> 1;
    const int g = lane >> 2, tg2 = (lane & 3)*2;
    const int rbase = wr*32;
    const int m0 = blockIdx.x*MB_, jg = blockIdx.y;
    const uint32_t sWu = (uint32_t)__cvta_generic_to_shared(sh_W);

#pragma unroll
    for (int it = 0; it < 4; it++) {
        int i = tid + it*NT_;
        int row = i >> 4, seg = (i & 15) << 3;
        *(uint4*)(sh_x + row*HP_ + seg) = *(const uint4*)(g_hH + (size_t)(m0 + row)*F_ + seg);
    }
    stage1(sWu, g_WA + (size_t)jg*16384, tid);
    cp_wait_all();
    __syncthreads();

    float acc[2][4][4];
#pragma unroll
    for (int mt = 0; mt < 2; mt++)
#pragma unroll
        for (int nt = 0; nt < 4; nt++) {
            int cc = jg*F_ + wc*32 + nt*8 + tg2;
            float2 b = *(const float2*)&bih[cc];
            acc[mt][nt][0]=b.x; acc[mt][nt][1]=b.y; acc[mt][nt][2]=b.x; acc[mt][nt][3]=b.y;
        }
    run_f16(acc, sh_x + rbase*HP_, sh_W, lane, wc);

#pragma unroll
    for (int mt = 0; mt < 2; mt++)
#pragma unroll
        for (int nt = 0; nt < 4; nt++) {
            int cc = jg*F_ + wc*32 + nt*8 + tg2;
#pragma unroll
            for (int p2 = 0; p2 < 2; p2++) {
                int n = m0 + rbase + mt*16 + g + p2*8;
                if (n < N_)
                    *(float2*)&g_P[(size_t)n*G3_ + cc] =
                        make_float2(acc[mt][nt][p2*2], acc[mt][nt][p2*2+1]);
            }
        }
}

// ---------------- GRU1: double-buffered weights, h-state in g_hf ----------------
__global__ void __launch_bounds__(NT_, 2) gru1_kernel(const float* __restrict__ bhh)
{
    extern __shared__ char smc[];
    __half* sh_ha = (__half*)smc;                        // 17408
    __half* sh_W0 = (__half*)(smc + 17408);              // 34816
    __half* sh_W1 = (__half*)(smc + 17408 + 34816);      // 34816
    float*  sh_bh = (float*)(smc + 17408 + 69632);       // 1536
    int*    sh_i  = (int*)(smc + 17408 + 69632 + 1536);  // 256

    const int tid = threadIdx.x, wid = tid >> 5, lane = tid & 31;
    const int wr = wid & 1, wc = wid >> 1;
    const int g = lane >> 2, tg2 = (lane & 3)*2;
    const int rbase = wr*32;
    const int m0 = blockIdx.x*MB_;
    uint32_t bufs[2] = { (uint32_t)__cvta_generic_to_shared(sh_W0),
                         (uint32_t)__cvta_generic_to_shared(sh_W1) };
    __half* shWp[2] = { sh_W0, sh_W1 };
    const __half* D[3] = { g_W1, g_W1 + 2*16384, g_W1 + 1*16384 };   // r, n, z

    for (int i = tid; i < G3_; i += NT_) sh_bh[i] = bhh[i];
    if (tid < MB_) sh_i[tid] = (int)g_upk[m0 + tid];
    // prologue: stage D_r for t=1
    stage1(bufs[0], D[0], tid);
    asm volatile("cp.async.commit_group;\n");
    __syncthreads();
    int pb = 0;

#pragma unroll 1
    for (int t = 0; t < L_; t++) {
        const bool doH = (t > 0);
        float rr[2][4][4], zz[2][4][4], acci[2][4][4], acch[2][4][4];

        // gate r
        if (doH) { phaseP(bufs[pb^1], D[1], tid); }
        load_gi1(rr, 0, t, sh_i, sh_bh, 1, rbase, g, tg2, wc);
        if (doH) { run_f16(rr, sh_ha + rbase*HP_, shWp[pb], lane, wc); pb ^= 1; }
#pragma unroll
        for (int mt=0; mt<2; mt++)
#pragma unroll
            for (int nt=0; nt<4; nt++)
#pragma unroll
                for (int q=0; q<4; q++) rr[mt][nt][q] = sigf(rr[mt][nt][q]);

        // gate n
        if (doH) { phaseP(bufs[pb^1], D[2], tid); }
        load_gi1(acci, 2, t, sh_i, nullptr, 0, rbase, g, tg2, wc);
#pragma unroll
        for (int mt=0; mt<2; mt++)
#pragma unroll
            for (int nt=0; nt<4; nt++) {
                int cc = 2*F_ + wc*32 + nt*8 + tg2;
                float2 bh = *(const float2*)&sh_bh[cc];
                acch[mt][nt][0]=bh.x; acch[mt][nt][1]=bh.y;
                acch[mt][nt][2]=bh.x; acch[mt][nt][3]=bh.y;
            }
        if (doH) { run_f16(acch, sh_ha + rbase*HP_, shWp[pb], lane, wc); pb ^= 1; }
        float nn[2][4][4];
#pragma unroll
        for (int mt=0; mt<2; mt++)
#pragma unroll
            for (int nt=0; nt<4; nt++)
#pragma unroll
                for (int q=0; q<4; q++)
                    nn[mt][nt][q] = tanh_s(acci[mt][nt][q] + rr[mt][nt][q]*acch[mt][nt][q]);

        // gate z
        if (doH) { phaseP(bufs[pb^1], D[0], tid); }
        load_gi1(zz, 1, t, sh_i, sh_bh, 1, rbase, g, tg2, wc);
        if (doH) { run_f16(zz, sh_ha + rbase*HP_, shWp[pb], lane, wc); pb ^= 1; }
#pragma unroll
        for (int mt=0; mt<2; mt++)
#pragma unroll
            for (int nt=0; nt<4; nt++)
#pragma unroll
                for (int q=0; q<4; q++) zz[mt][nt][q] = sigf(zz[mt][nt][q]);

        __syncthreads();   // all ha reads of this step complete
#pragma unroll
        for (int mt=0; mt<2; mt++)
#pragma unroll
            for (int nt=0; nt<4; nt++) {
                int cc = wc*32 + nt*8 + tg2;
#pragma unroll
                for (int p2=0; p2<2; p2++) {
                    int r = rbase + mt*16 + g + p2*8;
                    size_t hfb = (size_t)(m0 + r)*F_ + cc;
                    float h0o = 0.f, h1o = 0.f;
                    if (t > 0) { float2 ho = *(const float2*)&g_hf[hfb]; h0o = ho.x; h1o = ho.y; }
                    float n0 = nn[mt][nt][p2*2], n1 = nn[mt][nt][p2*2+1];
                    float z0 = zz[mt][nt][p2*2], z1 = zz[mt][nt][p2*2+1];
                    float h0 = (1.f - z0)*n0 + z0*h0o;
                    float h1 = (1.f - z1)*n1 + z1*h1o;
                    if (t < L_-1) *(float2*)&g_hf[hfb] = make_float2(h0, h1);
                    __half2 hv = __floats2half2_rn(h0, h1);
                    *(__half2*)&sh_ha[r*HP_ + cc] = hv;
                    *(__half2*)&g_ywH[((size_t)t*SEQ_ + m0 + r)*F_ + cc] = hv;
                }
            }
        __syncthreads();   // ha writes visible before next step's reads
    }
}

// ---------------- GRU2: double-buffered weights, h-state in g_hf ----------------
__global__ void __launch_bounds__(NT_, 2) gru2_kernel(const float* __restrict__ bhh,
                                                      float* __restrict__ hT_out)
{
    extern __shared__ char smc[];
    __half* sh_ha = (__half*)smc;                        // 17408
    __half* sh_x  = (__half*)(smc + 17408);              // 17408
    __half* sh_W0 = (__half*)(smc + 34816);              // 34816
    __half* sh_W1 = (__half*)(smc + 34816 + 34816);      // 34816
    float*  sh_bh = (float*)(smc + 34816 + 69632);       // 1536
    int*    sh_i  = (int*)(smc + 34816 + 69632 + 1536);  // 256

    const int tid = threadIdx.x, wid = tid >> 5, lane = tid & 31;
    const int wr = wid & 1, wc = wid >> 1;
    const int g = lane >> 2, tg2 = (lane & 3)*2;
    const int rbase = wr*32;
    const int m0 = blockIdx.x*MB_;
    uint32_t bufs[2] = { (uint32_t)__cvta_generic_to_shared(sh_W0),
                         (uint32_t)__cvta_generic_to_shared(sh_W1) };
    __half* shWp[2] = { sh_W0, sh_W1 };
    // chunk order per step: WXr, W2r, WXn, W2n, WXz, W2z
    const __half* C[6] = { g_WX, g_W2, g_WX + 2*16384, g_W2 + 2*16384,
                           g_WX + 1*16384, g_W2 + 1*16384 };

    for (int i = tid; i < G3_; i += NT_) sh_bh[i] = bhh[i];
#pragma unroll
    for (int it = 0; it < 4; it++) {
        int i = tid + it*NT_;
        int row = i >> 4, seg = (i & 15) << 3;
        *(uint4*)(sh_ha + row*HP_ + seg) =
            *(const uint4*)(g_ywH + ((size_t)(L_-1)*SEQ_ + m0 + row)*F_ + seg);
    }
    stage1(bufs[0], C[0], tid);
    asm volatile("cp.async.commit_group;\n");
    __syncthreads();
    int pb = 0;

#pragma unroll 1
    for (int t = 0; t < L_; t++) {
        // x tile + node indices (consumed after next phase's syncs)
#pragma unroll
        for (int it = 0; it < 4; it++) {
            int i = tid + it*NT_;
            int row = i >> 4, seg = (i & 15) << 3;
            *(uint4*)(sh_x + row*HP_ + seg) =
                *(const uint4*)(g_ywH + ((size_t)t*SEQ_ + m0 + row)*F_ + seg);
        }
        if (tid < MB_) sh_i[tid] = g_walksf[(size_t)(m0 + tid)*L_ + t];

        float rr[2][4][4], zz[2][4][4], acci[2][4][4], acch[2][4][4];

        // gate r
        phaseP(bufs[pb^1], C[1], tid);
        load_gi2(rr, 0, sh_i, sh_bh, 1, rbase, g, tg2, wc);
        run_f16(rr, sh_x + rbase*HP_, shWp[pb], lane, wc); pb ^= 1;
        phaseP(bufs[pb^1], C[2], tid);
        run_f16(rr, sh_ha + rbase*HP_, shWp[pb], lane, wc); pb ^= 1;
#pragma unroll
        for (int mt=0; mt<2; mt++)
#pragma unroll
            for (int nt=0; nt<4; nt++)
#pragma unroll
                for (int q=0; q<4; q++) rr[mt][nt][q] = sigf(rr[mt][nt][q]);

        // gate n
        phaseP(bufs[pb^1], C[3], tid);
        load_gi2(acci, 2, sh_i, nullptr, 0, rbase, g, tg2, wc);
#pragma unroll
        for (int mt=0; mt<2; mt++)
#pragma unroll
            for (int nt=0; nt<4; nt++) {
                int cc = 2*F_ + wc*32 + nt*8 + tg2;
                float2 bh = *(const float2*)&sh_bh[cc];
                acch[mt][nt][0]=bh.x; acch[mt][nt][1]=bh.y;
                acch[mt][nt][2]=bh.x; acch[mt][nt][3]=bh.y;
            }
        run_f16(acci, sh_x + rbase*HP_, shWp[pb], lane, wc); pb ^= 1;
        phaseP(bufs[pb^1], C[4], tid);
        run_f16(acch, sh_ha + rbase*HP_, shWp[pb], lane, wc); pb ^= 1;
        float nn[2][4][4];
#pragma unroll
        for (int mt=0; mt<2; mt++)
#pragma unroll
            for (int nt=0; nt<4; nt++)
#pragma unroll
                for (int q=0; q<4; q++)
                    nn[mt][nt][q] = tanh_s(acci[mt][nt][q] + rr[mt][nt][q]*acch[mt][nt][q]);

        // gate z
        phaseP(bufs[pb^1], C[5], tid);
        load_gi2(zz, 1, sh_i, sh_bh, 1, rbase, g, tg2, wc);
        run_f16(zz, sh_x + rbase*HP_, shWp[pb], lane, wc); pb ^= 1;
        phaseP(bufs[pb^1], C[0], tid);          // prefetch next step's first chunk
        run_f16(zz, sh_ha + rbase*HP_, shWp[pb], lane, wc); pb ^= 1;
#pragma unroll
        for (int mt=0; mt<2; mt++)
#pragma unroll
            for (int nt=0; nt<4; nt++)
#pragma unroll
                for (int q=0; q<4; q++) zz[mt][nt][q] = sigf(zz[mt][nt][q]);

        __syncthreads();   // all ha/x reads complete
#pragma unroll
        for (int mt=0; mt<2; mt++)
#pragma unroll
            for (int nt=0; nt<4; nt++) {
                int cc = wc*32 + nt*8 + tg2;
#pragma unroll
                for (int p2=0; p2<2; p2++) {
                    int r = rbase + mt*16 + g + p2*8;
                    size_t hfb = (size_t)(m0 + r)*F_ + cc;
                    float h0o, h1o;
                    if (t == 0) {
                        __half2 hv0 = *(const __half2*)&sh_ha[r*HP_ + cc];
                        h0o = __half2float(hv0.x); h1o = __half2float(hv0.y);
                    } else {
                        float2 ho = *(const float2*)&g_hf[hfb];
                        h0o = ho.x; h1o = ho.y;
                    }
                    float n0 = nn[mt][nt][p2*2], n1 = nn[mt][nt][p2*2+1];
                    float z0 = zz[mt][nt][p2*2], z1 = zz[mt][nt][p2*2+1];
                    float h0 = (1.f - z0)*n0 + z0*h0o;
                    float h1 = (1.f - z1)*n1 + z1*h1o;
                    if (t < L_-1) {
                        *(float2*)&g_hf[hfb] = make_float2(h0, h1);
                        *(__half2*)&sh_ha[r*HP_ + cc] = __floats2half2_rn(h0, h1);
                        if (g_need[m0 + r])
                            *(float2*)&g_yseq[t][((size_t)(m0+r))*F_ + cc] = make_float2(h0, h1);
                    } else {
                        *(float2*)&hT_out[((size_t)(m0+r))*F_ + cc] = make_float2(h0, h1);
                    }
                }
            }
        __syncthreads();   // ha/x writes ordered before next step
    }
}

// ---------------- loss ----------------
__global__ void lsum_kernel(const int* __restrict__ idxs, const float* __restrict__ y0)
{
    int b = blockIdx.x;
    int t = b % (L_-1), j = (b/(L_-1)) % SUB_, s = b/((L_-1)*SUB_);
    int seq = s*N_ + idxs[j];
    int node = g_walksf[(size_t)seq*L_ + t + 1];
    int o = threadIdx.x;
    __shared__ float red[OR_];
    red[o] = y0[(size_t)node*OR_ + o]; __syncthreads();
    for (int st = OR_/2; st > 0; st >>= 1) { if (o < st) red[o] += red[o+st]; __syncthreads(); }
    if (o == 0) g_part1[b] = red[0];
}

__global__ void lred1_kernel()
{
    __shared__ float red[256];
    int tid = threadIdx.x; float s = 0.f;
    for (int i = tid; i < NB_LOSS; i += 256) s += g_part1[i];
    red[tid] = s; __syncthreads();
    for (int st = 128; st > 0; st >>= 1) { if (tid < st) red[tid] += red[tid+st]; __syncthreads(); }
    if (tid == 0) g_posw = LOSS_CNT / red[0];
}

__global__ void lbce_kernel(const int* __restrict__ idxs, const float* __restrict__ y0,
                            const float* __restrict__ Wss, const float* __restrict__ bss)
{
    int b = blockIdx.x;
    int t = b % (L_-1), j = (b/(L_-1)) % SUB_, s = b/((L_-1)*SUB_);
    int seq = s*N_ + idxs[j];
    __shared__ float yrow[F_];
    int o = threadIdx.x;
    yrow[o]      = g_yseq[t][(size_t)seq*F_ + o];
    yrow[o + 64] = g_yseq[t][(size_t)seq*F_ + o + 64];
    __syncthreads();
    float acc = bss[o];
    const float4* wrp = (const float4*)(Wss + (size_t)o*F_);
#pragma unroll 8
    for (int k = 0; k < F_/4; k++) {
        float4 w = wrp[k];
        acc += yrow[k*4]*w.x + yrow[k*4+1]*w.y + yrow[k*4+2]*w.z + yrow[k*4+3]*w.w;
    }
    int node = g_walksf[(size_t)seq*L_ + t + 1];
    float yt = y0[(size_t)node*OR_ + o];
    float term = g_posw * yt * softplusf(-acc) + (1.f - yt) * softplusf(acc);
    __shared__ float red[OR_];
    red[o] = term; __syncthreads();
    for (int st = OR_/2; st > 0; st >>= 1) { if (o < st) red[o] += red[o+st]; __syncthreads(); }
    if (o == 0) g_part2[b] = red[0];
}

__global__ void lred2_kernel(float* __restrict__ dst)
{
    __shared__ float red[256];
    int tid = threadIdx.x; float s = 0.f;
    for (int i = tid; i < NB_LOSS; i += 256) s += g_part2[i];
    red[tid] = s; __syncthreads();
    for (int st = 128; st > 0; st >>= 1) { if (tid < st) red[tid] += red[tid+st]; __syncthreads(); }
    if (tid == 0) *dst = red[0] / LOSS_CNT;
}

// ---------------- launch ----------------
extern "C" void kernel_launch(void* const* d_in, const int* in_sizes, int n_in,
                              void* d_out, int out_size)
{
    const float* h     = (const float*)d_in[0];
    const float* y0    = (const float*)d_in[1];
    const float* Wih_w = (const float*)d_in[2];
    const float* Whh_w = (const float*)d_in[3];
    const float* bih_w = (const float*)d_in[4];
    const float* bhh_w = (const float*)d_in[5];
    const float* Wih   = (const float*)d_in[6];
    const float* Whh   = (const float*)d_in[7];
    const float* bih   = (const float*)d_in[8];
    const float* bhh   = (const float*)d_in[9];
    const float* W_ss  = (const float*)d_in[10];
    const float* b_ss  = (const float*)d_in[11];
    const int*   walks = (const int*)d_in[12];
    const int*   idxs  = (const int*)d_in[13];
    float* out = (float*)d_out;

    const int SMEM_PT = 17408 + 34816;                        // 52224
    const int SMEM_G1 = 17408 + 69632 + 1536 + 256;           // 88832
    const int SMEM_G2 = 34816 + 69632 + 1536 + 256;           // 106240
    cudaFuncSetAttribute(pT_kernel,   cudaFuncAttributeMaxDynamicSharedMemorySize, SMEM_PT);
    cudaFuncSetAttribute(gru1_kernel, cudaFuncAttributeMaxDynamicSharedMemorySize, SMEM_G1);
    cudaFuncSetAttribute(gru2_kernel, cudaFuncAttributeMaxDynamicSharedMemorySize, SMEM_G2);

    prep_kernel<<<(SEQ_ + 255)/256, 256>>>(walks);
    flag_kernel<<<(S_*SUB_ + 127)/128, 128>>>(idxs);
    wg_kernel<<<1, G3_>>>(Wih_w, bih_w);
    pack_kernel<<<(G3_*F_ + 255)/256, 256>>>(Whh_w, Whh, Wih);
    packh_kernel<<<(NP_*F_ + 255)/256, 256>>>(h);
    pT_kernel<<<dim3(PTILES_, 3), NT_, SMEM_PT>>>(bih);
    gru1_kernel<<<TILES_, NT_, SMEM_G1>>>(bhh_w);
    gru2_kernel<<<TILES_, NT_, SMEM_G2>>>(bhh, out);
    lsum_kernel<<<NB_LOSS, OR_>>>(idxs, y0);
    lred1_kernel<<<1, 256>>>();
    lbce_kernel<<<NB_LOSS, OR_>>>(idxs, y0, W_ss, b_ss);
    lred2_kernel<<<1, 256>>>(out + (out_size - 1));
}

// round 15
// speedup vs baseline: 1.1740x; 1.1740x over previous
#include <cuda_runtime.h>
#include <cuda_fp16.h>
#include <math.h>
#include <stdint.h>

#define S_    4
#define N_    10000
#define NP_   10048
#define L_    8
#define F_    128
#define G3_   384
#define OR_   64
#define SUB_  100
#define SEQ_  (S_*N_)
#define MB_   64
#define NT_   256
#define TILES_ (SEQ_/MB_)          // 625
#define PTILES_ (NP_/MB_)          // 157
#define NB_LOSS (S_*SUB_*(L_-1))
#define LOSS_CNT 179200.0f
#define HP_   136                  // fp16 tile pitch (bank-safe)
#define FP_   132                  // fp32 h-state pitch

__device__ int      g_walksf[SEQ_*L_];
__device__ unsigned g_upk[SEQ_];
__device__ float    g_wg[8*G3_];
__device__ float    g_P[N_*G3_];
__device__ __half   g_hH[(size_t)NP_*F_];             // h fp16
__device__ __half   g_ywH[(size_t)L_*SEQ_*F_];        // GRU1 out fp16
__device__ unsigned char g_need[SEQ_];
__device__ float    g_yseq[L_-1][SEQ_*F_];
__device__ float    g_part1[NB_LOSS];
__device__ float    g_part2[NB_LOSS];
__device__ float    g_posw;
__device__ __half   g_W1[G3_*F_];                     // Whh_w fp16
__device__ __half   g_W2[G3_*F_];                     // Whh fp16
__device__ __half   g_WX[G3_*F_];                     // Wih[:,128:256] fp16
__device__ __half   g_WA[G3_*F_];                     // Wih[:,0:128] fp16

__device__ __forceinline__ float sigf(float x) { return __fdividef(1.f, 1.f + __expf(-x)); }
__device__ __forceinline__ float tanh_s(float x) {
    float ax = fabsf(x); float e = __expf(-2.f*ax);
    return copysignf(__fdividef(1.f - e, 1.f + e), x);
}
__device__ __forceinline__ float softplusf(float x) {
    return fmaxf(x, 0.f) + log1pf(__expf(-fabsf(x)));
}

__device__ __forceinline__ void mma_f16(float c[4], uint32_t a0, uint32_t a1,
                                        uint32_t a2, uint32_t a3, uint32_t b0, uint32_t b1) {
    asm volatile("mma.sync.aligned.m16n8k16.row.col.f32.f16.f16.f32 "
                 "{%0,%1,%2,%3}, {%4,%5,%6,%7}, {%8,%9}, {%0,%1,%2,%3};\n"
                 : "+f"(c[0]), "+f"(c[1]), "+f"(c[2]), "+f"(c[3])
                 : "r"(a0), "r"(a1), "r"(a2), "r"(a3), "r"(b0), "r"(b1));
}
__device__ __forceinline__ void ldsm_x4(uint32_t& r0, uint32_t& r1, uint32_t& r2, uint32_t& r3,
                                        const void* p) {
    uint32_t a = (uint32_t)__cvta_generic_to_shared(p);
    asm volatile("ldmatrix.sync.aligned.m8n8.x4.shared.b16 {%0,%1,%2,%3}, [%4];"
                 : "=r"(r0), "=r"(r1), "=r"(r2), "=r"(r3) : "r"(a));
}

// fp16 single-pass GEMM: acc[2][4][4] += A(32x128, pitch HP_) @ W^T (128x128, pitch HP_)
__device__ __forceinline__ void run_f16(float (&acc)[2][4][4],
    const __half* __restrict__ A, const __half* __restrict__ W, int lane, int wc)
{
    const int rl = lane & 15;
    const int kp = (lane >> 4) << 3;
#pragma unroll
    for (int ks = 0; ks < 8; ks++) {
        const int k0 = ks*16 + kp;
        uint32_t a[2][4];
#pragma unroll
        for (int mt = 0; mt < 2; mt++)
            ldsm_x4(a[mt][0], a[mt][1], a[mt][2], a[mt][3], A + (mt*16 + rl)*HP_ + k0);
#pragma unroll
        for (int np = 0; np < 2; np++) {
            uint32_t b[4];
            ldsm_x4(b[0], b[1], b[2], b[3], W + (wc*32 + np*16 + rl)*HP_ + k0);
#pragma unroll
            for (int mt = 0; mt < 2; mt++) {
                mma_f16(acc[mt][np*2+0], a[mt][0], a[mt][1], a[mt][2], a[mt][3], b[0], b[2]);
                mma_f16(acc[mt][np*2+1], a[mt][0], a[mt][1], a[mt][2], a[mt][3], b[1], b[3]);
            }
        }
    }
}

__device__ __forceinline__ void cpa16(uint32_t d, const void* s) {
    asm volatile("cp.async.cg.shared.global [%0], [%1], 16;\n" :: "r"(d), "l"(s));
}
__device__ __forceinline__ void stage1(uint32_t dstB, const __half* __restrict__ src, int tid)
{
#pragma unroll
    for (int it = 0; it < 8; it++) {
        int i = tid + it*NT_;
        int row = i >> 4, seg = (i & 15) << 3;
        cpa16(dstB + (uint32_t)(row*HP_ + seg)*2u, src + row*128 + seg);
    }
}
__device__ __forceinline__ void cp_wait_all() {
    asm volatile("cp.async.commit_group;\n");
    asm volatile("cp.async.wait_group 0;\n" ::: "memory");
}

// gi loaders (fp32 sources)
__device__ __forceinline__ void load_gi1(float (&acc)[2][4][4], int jg, int t,
    const int* __restrict__ sh_i, const float* __restrict__ sh_bh, int addbias,
    int rbase, int g, int tg2, int wc)
{
#pragma unroll
    for (int mt = 0; mt < 2; mt++) {
        int u0 = (sh_i[rbase + mt*16 + g]     >> (4*t)) & 7;
        int u1 = (sh_i[rbase + mt*16 + g + 8] >> (4*t)) & 7;
#pragma unroll
        for (int nt = 0; nt < 4; nt++) {
            int cc = jg*F_ + wc*32 + nt*8 + tg2;
            float2 p0 = *(const float2*)&g_wg[u0*G3_ + cc];
            float2 p1 = *(const float2*)&g_wg[u1*G3_ + cc];
            acc[mt][nt][0]=p0.x; acc[mt][nt][1]=p0.y; acc[mt][nt][2]=p1.x; acc[mt][nt][3]=p1.y;
            if (addbias) {
                float2 bh = *(const float2*)&sh_bh[cc];
                acc[mt][nt][0]+=bh.x; acc[mt][nt][1]+=bh.y; acc[mt][nt][2]+=bh.x; acc[mt][nt][3]+=bh.y;
            }
        }
    }
}
__device__ __forceinline__ void load_gi2(float (&acc)[2][4][4], int jg,
    const int* __restrict__ sh_i, const float* __restrict__ sh_bh, int addbias,
    int rbase, int g, int tg2, int wc)
{
#pragma unroll
    for (int mt = 0; mt < 2; mt++) {
        int i0 = sh_i[rbase + mt*16 + g], i1 = sh_i[rbase + mt*16 + g + 8];
#pragma unroll
        for (int nt = 0; nt < 4; nt++) {
            int cc = jg*F_ + wc*32 + nt*8 + tg2;
            float2 p0 = *(const float2*)&g_P[(size_t)i0*G3_ + cc];
            float2 p1 = *(const float2*)&g_P[(size_t)i1*G3_ + cc];
            acc[mt][nt][0]=p0.x; acc[mt][nt][1]=p0.y; acc[mt][nt][2]=p1.x; acc[mt][nt][3]=p1.y;
            if (addbias) {
                float2 bh = *(const float2*)&sh_bh[cc];
                acc[mt][nt][0]+=bh.x; acc[mt][nt][1]+=bh.y; acc[mt][nt][2]+=bh.x; acc[mt][nt][3]+=bh.y;
            }
        }
    }
}

// ---------------- preprocessing ----------------
__global__ void prep_kernel(const int* __restrict__ walks)
{
    int m = blockIdx.x * blockDim.x + threadIdx.x;
    if (m >= SEQ_) return;
    int w[L_];
#pragma unroll
    for (int p = 0; p < L_; p++) w[p] = walks[m*L_ + p];
    unsigned pk = 0;
#pragma unroll
    for (int t = 0; t < L_; t++) {
        int p = L_-1-t, wp = w[p], u = p;
#pragma unroll
        for (int q = L_-1; q >= 0; q--) if (w[q] == wp) u = q;
        g_walksf[m*L_ + t] = wp;
        pk |= ((unsigned)u) << (4*t);
    }
    g_upk[m] = pk;
    g_need[m] = 0;
}

__global__ void flag_kernel(const int* __restrict__ idxs)
{
    int i = threadIdx.x + blockIdx.x*128;
    if (i >= S_*SUB_) return;
    int s = i / SUB_, j = i % SUB_;
    g_need[s*N_ + idxs[j]] = 1;
}

__global__ void wg_kernel(const float* __restrict__ Wih_w, const float* __restrict__ bih_w)
{
    int j = threadIdx.x;
    float b = bih_w[j];
#pragma unroll
    for (int u = 0; u < 8; u++) g_wg[u*G3_ + j] = Wih_w[j*8 + u] + b;
}

__global__ void pack_kernel(const float* __restrict__ Whh_w, const float* __restrict__ Whh,
                            const float* __restrict__ Wih)
{
    int i = blockIdx.x * 256 + threadIdx.x;
    if (i >= G3_*F_) return;
    g_W1[i] = __float2half(Whh_w[i]);
    g_W2[i] = __float2half(Whh[i]);
    int n = i >> 7, k = i & 127;
    g_WX[i] = __float2half(Wih[n*256 + 128 + k]);
    g_WA[i] = __float2half(Wih[n*256 + k]);
}

__global__ void packh_kernel(const float* __restrict__ h)
{
    int i = blockIdx.x * 256 + threadIdx.x;
    if (i >= NP_*F_) return;
    int n = i >> 7, k = i & 127;
    float v = (n < N_) ? h[(size_t)n*F_ + k] : 0.f;
    g_hH[(size_t)n*F_ + k] = __float2half(v);
}

// ---------------- P = h @ WihA^T + bih (fp16 tensor cores) ----------------
__global__ void __launch_bounds__(NT_) pT_kernel(const float* __restrict__ bih)
{
    extern __shared__ char smc[];
    __half* sh_x = (__half*)smc;                  // 17408
    __half* sh_W = (__half*)(smc + 17408);        // 34816

    const int tid = threadIdx.x, wid = tid >> 5, lane = tid & 31;
    const int wr = wid & 1, wc = wid >> 1;
    const int g = lane >> 2, tg2 = (lane & 3)*2;
    const int rbase = wr*32;
    const int m0 = blockIdx.x*MB_, jg = blockIdx.y;
    const uint32_t sWu = (uint32_t)__cvta_generic_to_shared(sh_W);

#pragma unroll
    for (int it = 0; it < 4; it++) {
        int i = tid + it*NT_;
        int row = i >> 4, seg = (i & 15) << 3;
        *(uint4*)(sh_x + row*HP_ + seg) = *(const uint4*)(g_hH + (size_t)(m0 + row)*F_ + seg);
    }
    stage1(sWu, g_WA + (size_t)jg*16384, tid);
    cp_wait_all();
    __syncthreads();

    float acc[2][4][4];
#pragma unroll
    for (int mt = 0; mt < 2; mt++)
#pragma unroll
        for (int nt = 0; nt < 4; nt++) {
            int cc = jg*F_ + wc*32 + nt*8 + tg2;
            float2 b = *(const float2*)&bih[cc];
            acc[mt][nt][0]=b.x; acc[mt][nt][1]=b.y; acc[mt][nt][2]=b.x; acc[mt][nt][3]=b.y;
        }
    run_f16(acc, sh_x + rbase*HP_, sh_W, lane, wc);

#pragma unroll
    for (int mt = 0; mt < 2; mt++)
#pragma unroll
        for (int nt = 0; nt < 4; nt++) {
            int cc = jg*F_ + wc*32 + nt*8 + tg2;
#pragma unroll
            for (int p2 = 0; p2 < 2; p2++) {
                int n = m0 + rbase + mt*16 + g + p2*8;
                if (n < N_)
                    *(float2*)&g_P[(size_t)n*G3_ + cc] =
                        make_float2(acc[mt][nt][p2*2], acc[mt][nt][p2*2+1]);
            }
        }
}

// ---------------- GRU1: fp16 single-pass, fp32 h state, 2 blocks/SM ----------------
__global__ void __launch_bounds__(NT_, 2) gru1_kernel(const float* __restrict__ bhh)
{
    extern __shared__ char smc[];
    float*  sh_hf = (float*)smc;                         // 33792
    __half* sh_ha = (__half*)(smc + 33792);              // 17408
    __half* sh_W  = (__half*)(smc + 33792 + 17408);      // 34816
    float*  sh_bh = (float*)(smc + 33792 + 17408 + 34816);  // 1536
    int*    sh_i  = (int*)(smc + 33792 + 17408 + 34816 + 1536);

    const int tid = threadIdx.x, wid = tid >> 5, lane = tid & 31;
    const int wr = wid & 1, wc = wid >> 1;
    const int g = lane >> 2, tg2 = (lane & 3)*2;
    const int rbase = wr*32;
    const int m0 = blockIdx.x*MB_;
    const uint32_t sWu = (uint32_t)__cvta_generic_to_shared(sh_W);

    for (int i = tid; i < G3_; i += NT_) sh_bh[i] = bhh[i];
    for (int i = tid; i < MB_*FP_; i += NT_) sh_hf[i] = 0.f;
    for (int i = tid; i < MB_*HP_/2; i += NT_) ((uint32_t*)sh_ha)[i] = 0u;
    if (tid < MB_) sh_i[tid] = (int)g_upk[m0 + tid];

#pragma unroll 1
    for (int t = 0; t < L_; t++) {
        const bool doH = (t > 0);
        float nn[2][4][4];
        {
            // gate r
            float rr[2][4][4];
            __syncthreads();
            if (doH) { stage1(sWu, g_W1, tid); cp_wait_all(); }
            __syncthreads();
            load_gi1(rr, 0, t, sh_i, sh_bh, 1, rbase, g, tg2, wc);
            if (doH) run_f16(rr, sh_ha + rbase*HP_, sh_W, lane, wc);
#pragma unroll
            for (int mt=0; mt<2; mt++)
#pragma unroll
                for (int nt=0; nt<4; nt++)
#pragma unroll
                    for (int q=0; q<4; q++) rr[mt][nt][q] = sigf(rr[mt][nt][q]);

            // gate n
            __syncthreads();
            if (doH) { stage1(sWu, g_W1 + 2*16384, tid); cp_wait_all(); }
            __syncthreads();
            float acci[2][4][4], acch[2][4][4];
            load_gi1(acci, 2, t, sh_i, nullptr, 0, rbase, g, tg2, wc);
#pragma unroll
            for (int mt=0; mt<2; mt++)
#pragma unroll
                for (int nt=0; nt<4; nt++) {
                    int cc = 2*F_ + wc*32 + nt*8 + tg2;
                    float2 bh = *(const float2*)&sh_bh[cc];
                    acch[mt][nt][0]=bh.x; acch[mt][nt][1]=bh.y;
                    acch[mt][nt][2]=bh.x; acch[mt][nt][3]=bh.y;
                }
            if (doH) run_f16(acch, sh_ha + rbase*HP_, sh_W, lane, wc);
#pragma unroll
            for (int mt=0; mt<2; mt++)
#pragma unroll
                for (int nt=0; nt<4; nt++)
#pragma unroll
                    for (int q=0; q<4; q++)
                        nn[mt][nt][q] = tanh_s(acci[mt][nt][q] + rr[mt][nt][q]*acch[mt][nt][q]);
        }

        // gate z
        float zz[2][4][4];
        __syncthreads();
        if (doH) { stage1(sWu, g_W1 + 1*16384, tid); cp_wait_all(); }
        __syncthreads();
        load_gi1(zz, 1, t, sh_i, sh_bh, 1, rbase, g, tg2, wc);
        if (doH) run_f16(zz, sh_ha + rbase*HP_, sh_W, lane, wc);
#pragma unroll
        for (int mt=0; mt<2; mt++)
#pragma unroll
            for (int nt=0; nt<4; nt++)
#pragma unroll
                for (int q=0; q<4; q++) zz[mt][nt][q] = sigf(zz[mt][nt][q]);

        __syncthreads();   // all GEMM reads of sh_ha complete
#pragma unroll
        for (int mt=0; mt<2; mt++)
#pragma unroll
            for (int nt=0; nt<4; nt++) {
                int cc = wc*32 + nt*8 + tg2;
#pragma unroll
                for (int p2=0; p2<2; p2++) {
                    int r = rbase + mt*16 + g + p2*8;
                    float n0 = nn[mt][nt][p2*2], n1 = nn[mt][nt][p2*2+1];
                    float z0 = zz[mt][nt][p2*2], z1 = zz[mt][nt][p2*2+1];
                    float2 ho = *(const float2*)&sh_hf[r*FP_ + cc];
                    float h0 = (1.f - z0)*n0 + z0*ho.x;
                    float h1 = (1.f - z1)*n1 + z1*ho.y;
                    *(float2*)&sh_hf[r*FP_ + cc] = make_float2(h0, h1);
                    __half2 hv = __floats2half2_rn(h0, h1);
                    *(__half2*)&sh_ha[r*HP_ + cc] = hv;
                    *(__half2*)&g_ywH[((size_t)t*SEQ_ + m0 + r)*F_ + cc] = hv;
                }
            }
    }
}

// ---------------- GRU2: fp16 single-pass, 2 blocks/SM ----------------
__device__ __forceinline__ void gate_gemm(float (&ax)[2][4][4], float (&ah2)[2][4][4], int jg,
    const __half* sh_x, const __half* sh_ha, uint32_t sWu, const __half* sh_W,
    int tid, int lane, int wc, int rbase)
{
    stage1(sWu, g_WX + (size_t)jg*16384, tid);
    cp_wait_all(); __syncthreads();
    run_f16(ax, sh_x + rbase*HP_, sh_W, lane, wc);
    __syncthreads();
    stage1(sWu, g_W2 + (size_t)jg*16384, tid);
    cp_wait_all(); __syncthreads();
    run_f16(ah2, sh_ha + rbase*HP_, sh_W, lane, wc);
}

__global__ void __launch_bounds__(NT_, 2) gru2_kernel(const float* __restrict__ bhh,
                                                      float* __restrict__ hT_out)
{
    extern __shared__ char smc[];
    float*  sh_hf = (float*)smc;                         // 33792
    __half* sh_ha = (__half*)(smc + 33792);              // 17408
    __half* sh_x  = (__half*)(smc + 33792 + 17408);      // 17408
    __half* sh_W  = (__half*)(smc + 33792 + 17408*2);    // 34816
    float*  sh_bh = (float*)(smc + 33792 + 17408*2 + 34816);
    int*    sh_i  = (int*)(smc + 33792 + 17408*2 + 34816 + 1536);

    const int tid = threadIdx.x, wid = tid >> 5, lane = tid & 31;
    const int wr = wid & 1, wc = wid >> 1;
    const int g = lane >> 2, tg2 = (lane & 3)*2;
    const int rbase = wr*32;
    const int m0 = blockIdx.x*MB_;
    const uint32_t sWu = (uint32_t)__cvta_generic_to_shared(sh_W);

    for (int i = tid; i < G3_; i += NT_) sh_bh[i] = bhh[i];
    for (int i = tid; i < MB_*F_; i += NT_) {
        int row = i >> 7, k = i & 127;
        __half v = g_ywH[((size_t)(L_-1)*SEQ_ + m0 + row)*F_ + k];
        sh_ha[row*HP_ + k] = v;
        sh_hf[row*FP_ + k] = __half2float(v);
    }

#pragma unroll 1
    for (int t = 0; t < L_; t++) {
        __syncthreads();   // prior step reads done
#pragma unroll
        for (int it = 0; it < 4; it++) {
            int i = tid + it*NT_;
            int row = i >> 4, seg = (i & 15) << 3;
            *(uint4*)(sh_x + row*HP_ + seg) =
                *(const uint4*)(g_ywH + ((size_t)t*SEQ_ + m0 + row)*F_ + seg);
        }
        if (tid < MB_) sh_i[tid] = g_walksf[(size_t)(m0 + tid)*L_ + t];
        __syncthreads();   // sh_x / sh_i visible

        float nn[2][4][4];
        {
            // gate r
            float rr[2][4][4];
            load_gi2(rr, 0, sh_i, sh_bh, 1, rbase, g, tg2, wc);
            gate_gemm(rr, rr, 0, sh_x, sh_ha, sWu, sh_W, tid, lane, wc, rbase);
#pragma unroll
            for (int mt=0; mt<2; mt++)
#pragma unroll
                for (int nt=0; nt<4; nt++)
#pragma unroll
                    for (int q=0; q<4; q++) rr[mt][nt][q] = sigf(rr[mt][nt][q]);

            // gate n
            __syncthreads();
            float acci[2][4][4], acch[2][4][4];
            load_gi2(acci, 2, sh_i, nullptr, 0, rbase, g, tg2, wc);
#pragma unroll
            for (int mt=0; mt<2; mt++)
#pragma unroll
                for (int nt=0; nt<4; nt++) {
                    int cc = 2*F_ + wc*32 + nt*8 + tg2;
                    float2 bh = *(const float2*)&sh_bh[cc];
                    acch[mt][nt][0]=bh.x; acch[mt][nt][1]=bh.y;
                    acch[mt][nt][2]=bh.x; acch[mt][nt][3]=bh.y;
                }
            gate_gemm(acci, acch, 2, sh_x, sh_ha, sWu, sh_W, tid, lane, wc, rbase);
#pragma unroll
            for (int mt=0; mt<2; mt++)
#pragma unroll
                for (int nt=0; nt<4; nt++)
#pragma unroll
                    for (int q=0; q<4; q++)
                        nn[mt][nt][q] = tanh_s(acci[mt][nt][q] + rr[mt][nt][q]*acch[mt][nt][q]);
        }

        // gate z
        float zz[2][4][4];
        __syncthreads();
        load_gi2(zz, 1, sh_i, sh_bh, 1, rbase, g, tg2, wc);
        gate_gemm(zz, zz, 1, sh_x, sh_ha, sWu, sh_W, tid, lane, wc, rbase);
#pragma unroll
        for (int mt=0; mt<2; mt++)
#pragma unroll
            for (int nt=0; nt<4; nt++)
#pragma unroll
                for (int q=0; q<4; q++) zz[mt][nt][q] = sigf(zz[mt][nt][q]);

        __syncthreads();   // all GEMM reads of sh_ha complete
#pragma unroll
        for (int mt=0; mt<2; mt++)
#pragma unroll
            for (int nt=0; nt<4; nt++) {
                int cc = wc*32 + nt*8 + tg2;
#pragma unroll
                for (int p2=0; p2<2; p2++) {
                    int r = rbase + mt*16 + g + p2*8;
                    float n0 = nn[mt][nt][p2*2], n1 = nn[mt][nt][p2*2+1];
                    float z0 = zz[mt][nt][p2*2], z1 = zz[mt][nt][p2*2+1];
                    float2 ho = *(const float2*)&sh_hf[r*FP_ + cc];
                    float h0 = (1.f - z0)*n0 + z0*ho.x;
                    float h1 = (1.f - z1)*n1 + z1*ho.y;
                    *(float2*)&sh_hf[r*FP_ + cc] = make_float2(h0, h1);
                    *(__half2*)&sh_ha[r*HP_ + cc] = __floats2half2_rn(h0, h1);
                    if (t < L_-1) {
                        if (g_need[m0 + r])
                            *(float2*)&g_yseq[t][((size_t)(m0+r))*F_ + cc] = make_float2(h0, h1);
                    } else {
                        *(float2*)&hT_out[((size_t)(m0+r))*F_ + cc] = make_float2(h0, h1);
                    }
                }
            }
    }
}

// ---------------- loss ----------------
__global__ void lsum_kernel(const int* __restrict__ idxs, const float* __restrict__ y0)
{
    int b = blockIdx.x;
    int t = b % (L_-1), j = (b/(L_-1)) % SUB_, s = b/((L_-1)*SUB_);
    int seq = s*N_ + idxs[j];
    int node = g_walksf[(size_t)seq*L_ + t + 1];
    int o = threadIdx.x;
    __shared__ float red[OR_];
    red[o] = y0[(size_t)node*OR_ + o]; __syncthreads();
    for (int st = OR_/2; st > 0; st >>= 1) { if (o < st) red[o] += red[o+st]; __syncthreads(); }
    if (o == 0) g_part1[b] = red[0];
}

__global__ void lred1_kernel()
{
    __shared__ float red[256];
    int tid = threadIdx.x; float s = 0.f;
    for (int i = tid; i < NB_LOSS; i += 256) s += g_part1[i];
    red[tid] = s; __syncthreads();
    for (int st = 128; st > 0; st >>= 1) { if (tid < st) red[tid] += red[tid+st]; __syncthreads(); }
    if (tid == 0) g_posw = LOSS_CNT / red[0];
}

__global__ void lbce_kernel(const int* __restrict__ idxs, const float* __restrict__ y0,
                            const float* __restrict__ Wss, const float* __restrict__ bss)
{
    int b = blockIdx.x;
    int t = b % (L_-1), j = (b/(L_-1)) % SUB_, s = b/((L_-1)*SUB_);
    int seq = s*N_ + idxs[j];
    __shared__ float yrow[F_];
    int o = threadIdx.x;
    yrow[o]      = g_yseq[t][(size_t)seq*F_ + o];
    yrow[o + 64] = g_yseq[t][(size_t)seq*F_ + o + 64];
    __syncthreads();
    float acc = bss[o];
    const float4* wrp = (const float4*)(Wss + (size_t)o*F_);
#pragma unroll 8
    for (int k = 0; k < F_/4; k++) {
        float4 w = wrp[k];
        acc += yrow[k*4]*w.x + yrow[k*4+1]*w.y + yrow[k*4+2]*w.z + yrow[k*4+3]*w.w;
    }
    int node = g_walksf[(size_t)seq*L_ + t + 1];
    float yt = y0[(size_t)node*OR_ + o];
    float term = g_posw * yt * softplusf(-acc) + (1.f - yt) * softplusf(acc);
    __shared__ float red[OR_];
    red[o] = term; __syncthreads();
    for (int st = OR_/2; st > 0; st >>= 1) { if (o < st) red[o] += red[o+st]; __syncthreads(); }
    if (o == 0) g_part2[b] = red[0];
}

__global__ void lred2_kernel(float* __restrict__ dst)
{
    __shared__ float red[256];
    int tid = threadIdx.x; float s = 0.f;
    for (int i = tid; i < NB_LOSS; i += 256) s += g_part2[i];
    red[tid] = s; __syncthreads();
    for (int st = 128; st > 0; st >>= 1) { if (tid < st) red[tid] += red[tid+st]; __syncthreads(); }
    if (tid == 0) *dst = red[0] / LOSS_CNT;
}

// ---------------- launch ----------------
extern "C" void kernel_launch(void* const* d_in, const int* in_sizes, int n_in,
                              void* d_out, int out_size)
{
    const float* h     = (const float*)d_in[0];
    const float* y0    = (const float*)d_in[1];
    const float* Wih_w = (const float*)d_in[2];
    const float* Whh_w = (const float*)d_in[3];
    const float* bih_w = (const float*)d_in[4];
    const float* bhh_w = (const float*)d_in[5];
    const float* Wih   = (const float*)d_in[6];
    const float* Whh   = (const float*)d_in[7];
    const float* bih   = (const float*)d_in[8];
    const float* bhh   = (const float*)d_in[9];
    const float* W_ss  = (const float*)d_in[10];
    const float* b_ss  = (const float*)d_in[11];
    const int*   walks = (const int*)d_in[12];
    const int*   idxs  = (const int*)d_in[13];
    float* out = (float*)d_out;

    const int SMEM_PT = 17408 + 34816;                        // 52224
    const int SMEM_G1 = 33792 + 17408 + 34816 + 1536 + 256;   // 87808
    const int SMEM_G2 = 33792 + 17408*2 + 34816 + 1536 + 256; // 105216
    cudaFuncSetAttribute(pT_kernel,   cudaFuncAttributeMaxDynamicSharedMemorySize, SMEM_PT);
    cudaFuncSetAttribute(gru1_kernel, cudaFuncAttributeMaxDynamicSharedMemorySize, SMEM_G1);
    cudaFuncSetAttribute(gru2_kernel, cudaFuncAttributeMaxDynamicSharedMemorySize, SMEM_G2);

    prep_kernel<<<(SEQ_ + 255)/256, 256>>>(walks);
    flag_kernel<<<(S_*SUB_ + 127)/128, 128>>>(idxs);
    wg_kernel<<<1, G3_>>>(Wih_w, bih_w);
    pack_kernel<<<(G3_*F_ + 255)/256, 256>>>(Whh_w, Whh, Wih);
    packh_kernel<<<(NP_*F_ + 255)/256, 256>>>(h);
    pT_kernel<<<dim3(PTILES_, 3), NT_, SMEM_PT>>>(bih);
    gru1_kernel<<<TILES_, NT_, SMEM_G1>>>(bhh_w);
    gru2_kernel<<<TILES_, NT_, SMEM_G2>>>(bhh, out);
    lsum_kernel<<<NB_LOSS, OR_>>>(idxs, y0);
    lred1_kernel<<<1, 256>>>();
    lbce_kernel<<<NB_LOSS, OR_>>>(idxs, y0, W_ss, b_ss);
    lred2_kernel<<<1, 256>>>(out + (out_size - 1));
}

// round 16
// speedup vs baseline: 1.4317x; 1.2195x over previous
#include <cuda_runtime.h>
#include <cuda_fp16.h>
#include <math.h>
#include <stdint.h>

#define S_    4
#define N_    10000
#define NP_   10048
#define L_    8
#define F_    128
#define G3_   384
#define OR_   64
#define SUB_  100
#define SEQ_  (S_*N_)
#define MB_   64
#define NT_   256
#define TILES_ (SEQ_/MB_)          // 625
#define PTILES_ (NP_/MB_)          // 157
#define TAB_  8192                 // dedup table (power of 2)
#define TTILES_ (TAB_/MB_)         // 128
#define NB_LOSS (S_*SUB_*(L_-1))
#define LOSS_CNT 179200.0f
#define HP_   136
#define FP_   132
#define KINV  0xFFFFFFFFu

__device__ int      g_walksf[SEQ_*L_];
__device__ unsigned g_upk[SEQ_];
__device__ unsigned g_tabkey[TAB_];
__device__ int      g_pid[SEQ_];
__device__ float    g_wg[8*G3_];
__device__ float    g_P[N_*G3_];
__device__ __half   g_hH[(size_t)NP_*F_];
__device__ __half   g_ywH[(size_t)L_*TAB_*F_];        // dedup GRU1 out fp16
__device__ unsigned char g_need[SEQ_];
__device__ float    g_yseq[L_-1][SEQ_*F_];
__device__ float    g_part1[NB_LOSS];
__device__ float    g_part2[NB_LOSS];
__device__ float    g_posw;
__device__ __half   g_W1[G3_*F_];
__device__ __half   g_W2[G3_*F_];
__device__ __half   g_WX[G3_*F_];
__device__ __half   g_WA[G3_*F_];

__device__ __forceinline__ float sigf(float x) { return __fdividef(1.f, 1.f + __expf(-x)); }
__device__ __forceinline__ float tanh_s(float x) {
    float ax = fabsf(x); float e = __expf(-2.f*ax);
    return copysignf(__fdividef(1.f - e, 1.f + e), x);
}
__device__ __forceinline__ float softplusf(float x) {
    return fmaxf(x, 0.f) + log1pf(__expf(-fabsf(x)));
}

__device__ __forceinline__ void mma_f16(float c[4], uint32_t a0, uint32_t a1,
                                        uint32_t a2, uint32_t a3, uint32_t b0, uint32_t b1) {
    asm volatile("mma.sync.aligned.m16n8k16.row.col.f32.f16.f16.f32 "
                 "{%0,%1,%2,%3}, {%4,%5,%6,%7}, {%8,%9}, {%0,%1,%2,%3};\n"
                 : "+f"(c[0]), "+f"(c[1]), "+f"(c[2]), "+f"(c[3])
                 : "r"(a0), "r"(a1), "r"(a2), "r"(a3), "r"(b0), "r"(b1));
}
__device__ __forceinline__ void ldsm_x4(uint32_t& r0, uint32_t& r1, uint32_t& r2, uint32_t& r3,
                                        const void* p) {
    uint32_t a = (uint32_t)__cvta_generic_to_shared(p);
    asm volatile("ldmatrix.sync.aligned.m8n8.x4.shared.b16 {%0,%1,%2,%3}, [%4];"
                 : "=r"(r0), "=r"(r1), "=r"(r2), "=r"(r3) : "r"(a));
}

// fp16 single-pass GEMM: acc[2][4][4] += A(32x128, pitch HP_) @ W^T (128x128, pitch HP_)
__device__ __forceinline__ void run_f16(float (&acc)[2][4][4],
    const __half* __restrict__ A, const __half* __restrict__ W, int lane, int wc)
{
    const int rl = lane & 15;
    const int kp = (lane >> 4) << 3;
#pragma unroll
    for (int ks = 0; ks < 8; ks++) {
        const int k0 = ks*16 + kp;
        uint32_t a[2][4];
#pragma unroll
        for (int mt = 0; mt < 2; mt++)
            ldsm_x4(a[mt][0], a[mt][1], a[mt][2], a[mt][3], A + (mt*16 + rl)*HP_ + k0);
#pragma unroll
        for (int np = 0; np < 2; np++) {
            uint32_t b[4];
            ldsm_x4(b[0], b[1], b[2], b[3], W + (wc*32 + np*16 + rl)*HP_ + k0);
#pragma unroll
            for (int mt = 0; mt < 2; mt++) {
                mma_f16(acc[mt][np*2+0], a[mt][0], a[mt][1], a[mt][2], a[mt][3], b[0], b[2]);
                mma_f16(acc[mt][np*2+1], a[mt][0], a[mt][1], a[mt][2], a[mt][3], b[1], b[3]);
            }
        }
    }
}

__device__ __forceinline__ void cpa16(uint32_t d, const void* s) {
    asm volatile("cp.async.cg.shared.global [%0], [%1], 16;\n" :: "r"(d), "l"(s));
}
__device__ __forceinline__ void stage1(uint32_t dstB, const __half* __restrict__ src, int tid)
{
#pragma unroll
    for (int it = 0; it < 8; it++) {
        int i = tid + it*NT_;
        int row = i >> 4, seg = (i & 15) << 3;
        cpa16(dstB + (uint32_t)(row*HP_ + seg)*2u, src + row*128 + seg);
    }
}
__device__ __forceinline__ void cp_wait_all() {
    asm volatile("cp.async.commit_group;\n");
    asm volatile("cp.async.wait_group 0;\n" ::: "memory");
}

// gi loaders
__device__ __forceinline__ void load_gi1(float (&acc)[2][4][4], int jg, int t,
    const unsigned* __restrict__ sh_k, const float* __restrict__ sh_bh, int addbias,
    int rbase, int g, int tg2, int wc)
{
#pragma unroll
    for (int mt = 0; mt < 2; mt++) {
        int u0 = (int)((sh_k[rbase + mt*16 + g]     >> (4*t)) & 7u);
        int u1 = (int)((sh_k[rbase + mt*16 + g + 8] >> (4*t)) & 7u);
#pragma unroll
        for (int nt = 0; nt < 4; nt++) {
            int cc = jg*F_ + wc*32 + nt*8 + tg2;
            float2 p0 = *(const float2*)&g_wg[u0*G3_ + cc];
            float2 p1 = *(const float2*)&g_wg[u1*G3_ + cc];
            acc[mt][nt][0]=p0.x; acc[mt][nt][1]=p0.y; acc[mt][nt][2]=p1.x; acc[mt][nt][3]=p1.y;
            if (addbias) {
                float2 bh = *(const float2*)&sh_bh[cc];
                acc[mt][nt][0]+=bh.x; acc[mt][nt][1]+=bh.y; acc[mt][nt][2]+=bh.x; acc[mt][nt][3]+=bh.y;
            }
        }
    }
}
__device__ __forceinline__ void load_gi2(float (&acc)[2][4][4], int jg,
    const int* __restrict__ sh_i, const float* __restrict__ sh_bh, int addbias,
    int rbase, int g, int tg2, int wc)
{
#pragma unroll
    for (int mt = 0; mt < 2; mt++) {
        int i0 = sh_i[rbase + mt*16 + g], i1 = sh_i[rbase + mt*16 + g + 8];
#pragma unroll
        for (int nt = 0; nt < 4; nt++) {
            int cc = jg*F_ + wc*32 + nt*8 + tg2;
            float2 p0 = *(const float2*)&g_P[(size_t)i0*G3_ + cc];
            float2 p1 = *(const float2*)&g_P[(size_t)i1*G3_ + cc];
            acc[mt][nt][0]=p0.x; acc[mt][nt][1]=p0.y; acc[mt][nt][2]=p1.x; acc[mt][nt][3]=p1.y;
            if (addbias) {
                float2 bh = *(const float2*)&sh_bh[cc];
                acc[mt][nt][0]+=bh.x; acc[mt][nt][1]+=bh.y; acc[mt][nt][2]+=bh.x; acc[mt][nt][3]+=bh.y;
            }
        }
    }
}

// ---------------- preprocessing ----------------
__global__ void prep_kernel(const int* __restrict__ walks)
{
    int m = blockIdx.x * blockDim.x + threadIdx.x;
    if (m >= SEQ_) return;
    int w[L_];
#pragma unroll
    for (int p = 0; p < L_; p++) w[p] = walks[m*L_ + p];
    unsigned pk = 0;
#pragma unroll
    for (int t = 0; t < L_; t++) {
        int p = L_-1-t, wp = w[p], u = p;
#pragma unroll
        for (int q = L_-1; q >= 0; q--) if (w[q] == wp) u = q;
        g_walksf[m*L_ + t] = wp;
        pk |= ((unsigned)u) << (4*t);
    }
    g_upk[m] = pk;
    g_need[m] = 0;
}

__global__ void tabinit_kernel()
{
    int i = blockIdx.x*256 + threadIdx.x;
    if (i < TAB_) g_tabkey[i] = KINV;
}

__global__ void dedup_kernel()
{
    int m = blockIdx.x*256 + threadIdx.x;
    if (m >= SEQ_) return;
    unsigned key = g_upk[m];
    unsigned hx = (key * 2654435761u) >> 19;   // 13 bits
    for (;;) {
        unsigned prev = atomicCAS(&g_tabkey[hx], KINV, key);
        if (prev == KINV || prev == key) { g_pid[m] = (int)hx; break; }
        hx = (hx + 1) & (TAB_ - 1);
    }
}

__global__ void flag_kernel(const int* __restrict__ idxs)
{
    int i = threadIdx.x + blockIdx.x*128;
    if (i >= S_*SUB_) return;
    int s = i / SUB_, j = i % SUB_;
    g_need[s*N_ + idxs[j]] = 1;
}

__global__ void wg_kernel(const float* __restrict__ Wih_w, const float* __restrict__ bih_w)
{
    int j = threadIdx.x;
    float b = bih_w[j];
#pragma unroll
    for (int u = 0; u < 8; u++) g_wg[u*G3_ + j] = Wih_w[j*8 + u] + b;
}

__global__ void pack_kernel(const float* __restrict__ Whh_w, const float* __restrict__ Whh,
                            const float* __restrict__ Wih)
{
    int i = blockIdx.x * 256 + threadIdx.x;
    if (i >= G3_*F_) return;
    g_W1[i] = __float2half(Whh_w[i]);
    g_W2[i] = __float2half(Whh[i]);
    int n = i >> 7, k = i & 127;
    g_WX[i] = __float2half(Wih[n*256 + 128 + k]);
    g_WA[i] = __float2half(Wih[n*256 + k]);
}

__global__ void packh_kernel(const float* __restrict__ h)
{
    int i = blockIdx.x * 256 + threadIdx.x;
    if (i >= NP_*F_) return;
    int n = i >> 7, k = i & 127;
    float v = (n < N_) ? h[(size_t)n*F_ + k] : 0.f;
    g_hH[(size_t)n*F_ + k] = __float2half(v);
}

// ---------------- P = h @ WihA^T + bih ----------------
__global__ void __launch_bounds__(NT_) pT_kernel(const float* __restrict__ bih)
{
    extern __shared__ char smc[];
    __half* sh_x = (__half*)smc;
    __half* sh_W = (__half*)(smc + 17408);

    const int tid = threadIdx.x, wid = tid >> 5, lane = tid & 31;
    const int wr = wid & 1, wc = wid >> 1;
    const int g = lane >> 2, tg2 = (lane & 3)*2;
    const int rbase = wr*32;
    const int m0 = blockIdx.x*MB_, jg = blockIdx.y;
    const uint32_t sWu = (uint32_t)__cvta_generic_to_shared(sh_W);

#pragma unroll
    for (int it = 0; it < 4; it++) {
        int i = tid + it*NT_;
        int row = i >> 4, seg = (i & 15) << 3;
        *(uint4*)(sh_x + row*HP_ + seg) = *(const uint4*)(g_hH + (size_t)(m0 + row)*F_ + seg);
    }
    stage1(sWu, g_WA + (size_t)jg*16384, tid);
    cp_wait_all();
    __syncthreads();

    float acc[2][4][4];
#pragma unroll
    for (int mt = 0; mt < 2; mt++)
#pragma unroll
        for (int nt = 0; nt < 4; nt++) {
            int cc = jg*F_ + wc*32 + nt*8 + tg2;
            float2 b = *(const float2*)&bih[cc];
            acc[mt][nt][0]=b.x; acc[mt][nt][1]=b.y; acc[mt][nt][2]=b.x; acc[mt][nt][3]=b.y;
        }
    run_f16(acc, sh_x + rbase*HP_, sh_W, lane, wc);

#pragma unroll
    for (int mt = 0; mt < 2; mt++)
#pragma unroll
        for (int nt = 0; nt < 4; nt++) {
            int cc = jg*F_ + wc*32 + nt*8 + tg2;
#pragma unroll
            for (int p2 = 0; p2 < 2; p2++) {
                int n = m0 + rbase + mt*16 + g + p2*8;
                if (n < N_)
                    *(float2*)&g_P[(size_t)n*G3_ + cc] =
                        make_float2(acc[mt][nt][p2*2], acc[mt][nt][p2*2+1]);
            }
        }
}

// ---------------- GRU1 over dedup table slots ----------------
__global__ void __launch_bounds__(NT_, 2) gru1_kernel(const float* __restrict__ bhh)
{
    extern __shared__ char smc[];
    float*  sh_hf = (float*)smc;                         // 33792
    __half* sh_ha = (__half*)(smc + 33792);              // 17408
    __half* sh_W  = (__half*)(smc + 33792 + 17408);      // 34816
    float*  sh_bh = (float*)(smc + 33792 + 17408 + 34816);
    unsigned* sh_k = (unsigned*)(smc + 33792 + 17408 + 34816 + 1536);

    const int tid = threadIdx.x, wid = tid >> 5, lane = tid & 31;
    const int wr = wid & 1, wc = wid >> 1;
    const int g = lane >> 2, tg2 = (lane & 3)*2;
    const int rbase = wr*32;
    const int m0 = blockIdx.x*MB_;
    const uint32_t sWu = (uint32_t)__cvta_generic_to_shared(sh_W);

    if (tid < MB_) sh_k[tid] = g_tabkey[m0 + tid];
    __syncthreads();
    // early-exit if whole block's slots are empty
    {
        int any = 0;
        if (tid < MB_ && sh_k[tid] != KINV) any = 1;
        if (!__syncthreads_or(any)) return;
    }
    for (int i = tid; i < G3_; i += NT_) sh_bh[i] = bhh[i];
    for (int i = tid; i < MB_*FP_; i += NT_) sh_hf[i] = 0.f;
    for (int i = tid; i < MB_*HP_/2; i += NT_) ((uint32_t*)sh_ha)[i] = 0u;

#pragma unroll 1
    for (int t = 0; t < L_; t++) {
        const bool doH = (t > 0);
        float nn[2][4][4];
        {
            float rr[2][4][4];
            __syncthreads();
            if (doH) { stage1(sWu, g_W1, tid); cp_wait_all(); }
            __syncthreads();
            load_gi1(rr, 0, t, sh_k, sh_bh, 1, rbase, g, tg2, wc);
            if (doH) run_f16(rr, sh_ha + rbase*HP_, sh_W, lane, wc);
#pragma unroll
            for (int mt=0; mt<2; mt++)
#pragma unroll
                for (int nt=0; nt<4; nt++)
#pragma unroll
                    for (int q=0; q<4; q++) rr[mt][nt][q] = sigf(rr[mt][nt][q]);

            __syncthreads();
            if (doH) { stage1(sWu, g_W1 + 2*16384, tid); cp_wait_all(); }
            __syncthreads();
            float acci[2][4][4], acch[2][4][4];
            load_gi1(acci, 2, t, sh_k, nullptr, 0, rbase, g, tg2, wc);
#pragma unroll
            for (int mt=0; mt<2; mt++)
#pragma unroll
                for (int nt=0; nt<4; nt++) {
                    int cc = 2*F_ + wc*32 + nt*8 + tg2;
                    float2 bh = *(const float2*)&sh_bh[cc];
                    acch[mt][nt][0]=bh.x; acch[mt][nt][1]=bh.y;
                    acch[mt][nt][2]=bh.x; acch[mt][nt][3]=bh.y;
                }
            if (doH) run_f16(acch, sh_ha + rbase*HP_, sh_W, lane, wc);
#pragma unroll
            for (int mt=0; mt<2; mt++)
#pragma unroll
                for (int nt=0; nt<4; nt++)
#pragma unroll
                    for (int q=0; q<4; q++)
                        nn[mt][nt][q] = tanh_s(acci[mt][nt][q] + rr[mt][nt][q]*acch[mt][nt][q]);
        }

        float zz[2][4][4];
        __syncthreads();
        if (doH) { stage1(sWu, g_W1 + 1*16384, tid); cp_wait_all(); }
        __syncthreads();
        load_gi1(zz, 1, t, sh_k, sh_bh, 1, rbase, g, tg2, wc);
        if (doH) run_f16(zz, sh_ha + rbase*HP_, sh_W, lane, wc);
#pragma unroll
        for (int mt=0; mt<2; mt++)
#pragma unroll
            for (int nt=0; nt<4; nt++)
#pragma unroll
                for (int q=0; q<4; q++) zz[mt][nt][q] = sigf(zz[mt][nt][q]);

        __syncthreads();
#pragma unroll
        for (int mt=0; mt<2; mt++)
#pragma unroll
            for (int nt=0; nt<4; nt++) {
                int cc = wc*32 + nt*8 + tg2;
#pragma unroll
                for (int p2=0; p2<2; p2++) {
                    int r = rbase + mt*16 + g + p2*8;
                    float n0 = nn[mt][nt][p2*2], n1 = nn[mt][nt][p2*2+1];
                    float z0 = zz[mt][nt][p2*2], z1 = zz[mt][nt][p2*2+1];
                    float2 ho = *(const float2*)&sh_hf[r*FP_ + cc];
                    float h0 = (1.f - z0)*n0 + z0*ho.x;
                    float h1 = (1.f - z1)*n1 + z1*ho.y;
                    *(float2*)&sh_hf[r*FP_ + cc] = make_float2(h0, h1);
                    __half2 hv = __floats2half2_rn(h0, h1);
                    *(__half2*)&sh_ha[r*HP_ + cc] = hv;
                    *(__half2*)&g_ywH[((size_t)t*TAB_ + m0 + r)*F_ + cc] = hv;
                }
            }
    }
}

// ---------------- GRU2: fp16 single-pass, x gathered via pid ----------------
__device__ __forceinline__ void gate_gemm(float (&ax)[2][4][4], float (&ah2)[2][4][4], int jg,
    const __half* sh_x, const __half* sh_ha, uint32_t sWu, const __half* sh_W,
    int tid, int lane, int wc, int rbase)
{
    stage1(sWu, g_WX + (size_t)jg*16384, tid);
    cp_wait_all(); __syncthreads();
    run_f16(ax, sh_x + rbase*HP_, sh_W, lane, wc);
    __syncthreads();
    stage1(sWu, g_W2 + (size_t)jg*16384, tid);
    cp_wait_all(); __syncthreads();
    run_f16(ah2, sh_ha + rbase*HP_, sh_W, lane, wc);
}

__global__ void __launch_bounds__(NT_, 2) gru2_kernel(const float* __restrict__ bhh,
                                                      float* __restrict__ hT_out)
{
    extern __shared__ char smc[];
    float*  sh_hf = (float*)smc;                         // 33792
    __half* sh_ha = (__half*)(smc + 33792);              // 17408
    __half* sh_x  = (__half*)(smc + 33792 + 17408);      // 17408
    __half* sh_W  = (__half*)(smc + 33792 + 17408*2);    // 34816
    float*  sh_bh = (float*)(smc + 33792 + 17408*2 + 34816);    // 1536
    int*    sh_i  = (int*)(smc + 33792 + 17408*2 + 34816 + 1536);  // 256
    int*    sh_pid = (int*)(smc + 33792 + 17408*2 + 34816 + 1536 + 256);  // 256

    const int tid = threadIdx.x, wid = tid >> 5, lane = tid & 31;
    const int wr = wid & 1, wc = wid >> 1;
    const int g = lane >> 2, tg2 = (lane & 3)*2;
    const int rbase = wr*32;
    const int m0 = blockIdx.x*MB_;
    const uint32_t sWu = (uint32_t)__cvta_generic_to_shared(sh_W);

    for (int i = tid; i < G3_; i += NT_) sh_bh[i] = bhh[i];
    if (tid < MB_) sh_pid[tid] = g_pid[m0 + tid];
    __syncthreads();
    for (int i = tid; i < MB_*F_; i += NT_) {
        int row = i >> 7, k = i & 127;
        __half v = g_ywH[((size_t)(L_-1)*TAB_ + sh_pid[row])*F_ + k];
        sh_ha[row*HP_ + k] = v;
        sh_hf[row*FP_ + k] = __half2float(v);
    }

#pragma unroll 1
    for (int t = 0; t < L_; t++) {
        __syncthreads();
#pragma unroll
        for (int it = 0; it < 4; it++) {
            int i = tid + it*NT_;
            int row = i >> 4, seg = (i & 15) << 3;
            *(uint4*)(sh_x + row*HP_ + seg) =
                *(const uint4*)(g_ywH + ((size_t)t*TAB_ + sh_pid[row])*F_ + seg);
        }
        if (tid < MB_) sh_i[tid] = g_walksf[(size_t)(m0 + tid)*L_ + t];
        __syncthreads();

        float nn[2][4][4];
        {
            float rr[2][4][4];
            load_gi2(rr, 0, sh_i, sh_bh, 1, rbase, g, tg2, wc);
            gate_gemm(rr, rr, 0, sh_x, sh_ha, sWu, sh_W, tid, lane, wc, rbase);
#pragma unroll
            for (int mt=0; mt<2; mt++)
#pragma unroll
                for (int nt=0; nt<4; nt++)
#pragma unroll
                    for (int q=0; q<4; q++) rr[mt][nt][q] = sigf(rr[mt][nt][q]);

            __syncthreads();
            float acci[2][4][4], acch[2][4][4];
            load_gi2(acci, 2, sh_i, nullptr, 0, rbase, g, tg2, wc);
#pragma unroll
            for (int mt=0; mt<2; mt++)
#pragma unroll
                for (int nt=0; nt<4; nt++) {
                    int cc = 2*F_ + wc*32 + nt*8 + tg2;
                    float2 bh = *(const float2*)&sh_bh[cc];
                    acch[mt][nt][0]=bh.x; acch[mt][nt][1]=bh.y;
                    acch[mt][nt][2]=bh.x; acch[mt][nt][3]=bh.y;
                }
            gate_gemm(acci, acch, 2, sh_x, sh_ha, sWu, sh_W, tid, lane, wc, rbase);
#pragma unroll
            for (int mt=0; mt<2; mt++)
#pragma unroll
                for (int nt=0; nt<4; nt++)
#pragma unroll
                    for (int q=0; q<4; q++)
                        nn[mt][nt][q] = tanh_s(acci[mt][nt][q] + rr[mt][nt][q]*acch[mt][nt][q]);
        }

        float zz[2][4][4];
        __syncthreads();
        load_gi2(zz, 1, sh_i, sh_bh, 1, rbase, g, tg2, wc);
        gate_gemm(zz, zz, 1, sh_x, sh_ha, sWu, sh_W, tid, lane, wc, rbase);
#pragma unroll
        for (int mt=0; mt<2; mt++)
#pragma unroll
            for (int nt=0; nt<4; nt++)
#pragma unroll
                for (int q=0; q<4; q++) zz[mt][nt][q] = sigf(zz[mt][nt][q]);

        __syncthreads();
#pragma unroll
        for (int mt=0; mt<2; mt++)
#pragma unroll
            for (int nt=0; nt<4; nt++) {
                int cc = wc*32 + nt*8 + tg2;
#pragma unroll
                for (int p2=0; p2<2; p2++) {
                    int r = rbase + mt*16 + g + p2*8;
                    float n0 = nn[mt][nt][p2*2], n1 = nn[mt][nt][p2*2+1];
                    float z0 = zz[mt][nt][p2*2], z1 = zz[mt][nt][p2*2+1];
                    float2 ho = *(const float2*)&sh_hf[r*FP_ + cc];
                    float h0 = (1.f - z0)*n0 + z0*ho.x;
                    float h1 = (1.f - z1)*n1 + z1*ho.y;
                    *(float2*)&sh_hf[r*FP_ + cc] = make_float2(h0, h1);
                    *(__half2*)&sh_ha[r*HP_ + cc] = __floats2half2_rn(h0, h1);
                    if (t < L_-1) {
                        if (g_need[m0 + r])
                            *(float2*)&g_yseq[t][((size_t)(m0+r))*F_ + cc] = make_float2(h0, h1);
                    } else {
                        *(float2*)&hT_out[((size_t)(m0+r))*F_ + cc] = make_float2(h0, h1);
                    }
                }
            }
    }
}

// ---------------- loss ----------------
__global__ void lsum_kernel(const int* __restrict__ idxs, const float* __restrict__ y0)
{
    int b = blockIdx.x;
    int t = b % (L_-1), j = (b/(L_-1)) % SUB_, s = b/((L_-1)*SUB_);
    int seq = s*N_ + idxs[j];
    int node = g_walksf[(size_t)seq*L_ + t + 1];
    int o = threadIdx.x;
    __shared__ float red[OR_];
    red[o] = y0[(size_t)node*OR_ + o]; __syncthreads();
    for (int st = OR_/2; st > 0; st >>= 1) { if (o < st) red[o] += red[o+st]; __syncthreads(); }
    if (o == 0) g_part1[b] = red[0];
}

__global__ void lred1_kernel()
{
    __shared__ float red[256];
    int tid = threadIdx.x; float s = 0.f;
    for (int i = tid; i < NB_LOSS; i += 256) s += g_part1[i];
    red[tid] = s; __syncthreads();
    for (int st = 128; st > 0; st >>= 1) { if (tid < st) red[tid] += red[tid+st]; __syncthreads(); }
    if (tid == 0) g_posw = LOSS_CNT / red[0];
}

__global__ void lbce_kernel(const int* __restrict__ idxs, const float* __restrict__ y0,
                            const float* __restrict__ Wss, const float* __restrict__ bss)
{
    int b = blockIdx.x;
    int t = b % (L_-1), j = (b/(L_-1)) % SUB_, s = b/((L_-1)*SUB_);
    int seq = s*N_ + idxs[j];
    __shared__ float yrow[F_];
    int o = threadIdx.x;
    yrow[o]      = g_yseq[t][(size_t)seq*F_ + o];
    yrow[o + 64] = g_yseq[t][(size_t)seq*F_ + o + 64];
    __syncthreads();
    float acc = bss[o];
    const float4* wrp = (const float4*)(Wss + (size_t)o*F_);
#pragma unroll 8
    for (int k = 0; k < F_/4; k++) {
        float4 w = wrp[k];
        acc += yrow[k*4]*w.x + yrow[k*4+1]*w.y + yrow[k*4+2]*w.z + yrow[k*4+3]*w.w;
    }
    int node = g_walksf[(size_t)seq*L_ + t + 1];
    float yt = y0[(size_t)node*OR_ + o];
    float term = g_posw * yt * softplusf(-acc) + (1.f - yt) * softplusf(acc);
    __shared__ float red[OR_];
    red[o] = term; __syncthreads();
    for (int st = OR_/2; st > 0; st >>= 1) { if (o < st) red[o] += red[o+st]; __syncthreads(); }
    if (o == 0) g_part2[b] = red[0];
}

__global__ void lred2_kernel(float* __restrict__ dst)
{
    __shared__ float red[256];
    int tid = threadIdx.x; float s = 0.f;
    for (int i = tid; i < NB_LOSS; i += 256) s += g_part2[i];
    red[tid] = s; __syncthreads();
    for (int st = 128; st > 0; st >>= 1) { if (tid < st) red[tid] += red[tid+st]; __syncthreads(); }
    if (tid == 0) *dst = red[0] / LOSS_CNT;
}

// ---------------- launch ----------------
extern "C" void kernel_launch(void* const* d_in, const int* in_sizes, int n_in,
                              void* d_out, int out_size)
{
    const float* h     = (const float*)d_in[0];
    const float* y0    = (const float*)d_in[1];
    const float* Wih_w = (const float*)d_in[2];
    const float* Whh_w = (const float*)d_in[3];
    const float* bih_w = (const float*)d_in[4];
    const float* bhh_w = (const float*)d_in[5];
    const float* Wih   = (const float*)d_in[6];
    const float* Whh   = (const float*)d_in[7];
    const float* bih   = (const float*)d_in[8];
    const float* bhh   = (const float*)d_in[9];
    const float* W_ss  = (const float*)d_in[10];
    const float* b_ss  = (const float*)d_in[11];
    const int*   walks = (const int*)d_in[12];
    const int*   idxs  = (const int*)d_in[13];
    float* out = (float*)d_out;

    const int SMEM_PT = 17408 + 34816;
    const int SMEM_G1 = 33792 + 17408 + 34816 + 1536 + 256;          // 87808
    const int SMEM_G2 = 33792 + 17408*2 + 34816 + 1536 + 256 + 256;  // 105472
    cudaFuncSetAttribute(pT_kernel,   cudaFuncAttributeMaxDynamicSharedMemorySize, SMEM_PT);
    cudaFuncSetAttribute(gru1_kernel, cudaFuncAttributeMaxDynamicSharedMemorySize, SMEM_G1);
    cudaFuncSetAttribute(gru2_kernel, cudaFuncAttributeMaxDynamicSharedMemorySize, SMEM_G2);

    prep_kernel<<<(SEQ_ + 255)/256, 256>>>(walks);
    tabinit_kernel<<<(TAB_ + 255)/256, 256>>>();
    dedup_kernel<<<(SEQ_ + 255)/256, 256>>>();
    flag_kernel<<<(S_*SUB_ + 127)/128, 128>>>(idxs);
    wg_kernel<<<1, G3_>>>(Wih_w, bih_w);
    pack_kernel<<<(G3_*F_ + 255)/256, 256>>>(Whh_w, Whh, Wih);
    packh_kernel<<<(NP_*F_ + 255)/256, 256>>>(h);
    pT_kernel<<<dim3(PTILES_, 3), NT_, SMEM_PT>>>(bih);
    gru1_kernel<<<TTILES_, NT_, SMEM_G1>>>(bhh_w);
    gru2_kernel<<<TILES_, NT_, SMEM_G2>>>(bhh, out);
    lsum_kernel<<<NB_LOSS, OR_>>>(idxs, y0);
    lred1_kernel<<<1, 256>>>();
    lbce_kernel<<<NB_LOSS, OR_>>>(idxs, y0, W_ss, b_ss);
    lred2_kernel<<<1, 256>>>(out + (out_size - 1));
}

// round 17
// speedup vs baseline: 1.9305x; 1.3484x over previous
#include <cuda_runtime.h>
#include <cuda_fp16.h>
#include <math.h>
#include <stdint.h>

#define S_    4
#define N_    10000
#define NP_   10048
#define L_    8
#define F_    128
#define G3_   384
#define OR_   64
#define SUB_  100
#define SEQ_  (S_*N_)
#define MB_   64
#define NT_   256
#define TILES_ (SEQ_/MB_)          // 625
#define PTILES_ (NP_/MB_)          // 157
#define TAB_  8192
#define TTILES_ (TAB_/MB_)         // 128
#define NB_LOSS (S_*SUB_*(L_-1))
#define LOSS_CNT 179200.0f
#define HP_   136
#define FP_   132
#define KINV  0xFFFFFFFFu

__device__ int      g_walksf[SEQ_*L_];
__device__ unsigned g_upk[SEQ_];
__device__ unsigned g_tabkey[TAB_];
__device__ int      g_pid[SEQ_];
__device__ float    g_wg[8*G3_];
__device__ float    g_P[N_*G3_];
__device__ __half   g_hH[(size_t)NP_*F_];
__device__ __half   g_ywH[(size_t)L_*TAB_*F_];        // dedup GRU1 out fp16
__device__ float    g_GX[(size_t)L_*TAB_*G3_];        // dedup x@WX^T (fp32)
__device__ unsigned char g_need[SEQ_];
__device__ float    g_yseq[L_-1][SEQ_*F_];
__device__ float    g_part1[NB_LOSS];
__device__ float    g_part2[NB_LOSS];
__device__ float    g_posw;
__device__ __half   g_W1[G3_*F_];
__device__ __half   g_W2[G3_*F_];
__device__ __half   g_WX[G3_*F_];
__device__ __half   g_WA[G3_*F_];

__device__ __forceinline__ float sigf(float x) { return __fdividef(1.f, 1.f + __expf(-x)); }
__device__ __forceinline__ float tanh_s(float x) {
    float ax = fabsf(x); float e = __expf(-2.f*ax);
    return copysignf(__fdividef(1.f - e, 1.f + e), x);
}
__device__ __forceinline__ float softplusf(float x) {
    return fmaxf(x, 0.f) + log1pf(__expf(-fabsf(x)));
}

__device__ __forceinline__ void mma_f16(float c[4], uint32_t a0, uint32_t a1,
                                        uint32_t a2, uint32_t a3, uint32_t b0, uint32_t b1) {
    asm volatile("mma.sync.aligned.m16n8k16.row.col.f32.f16.f16.f32 "
                 "{%0,%1,%2,%3}, {%4,%5,%6,%7}, {%8,%9}, {%0,%1,%2,%3};\n"
                 : "+f"(c[0]), "+f"(c[1]), "+f"(c[2]), "+f"(c[3])
                 : "r"(a0), "r"(a1), "r"(a2), "r"(a3), "r"(b0), "r"(b1));
}
__device__ __forceinline__ void ldsm_x4(uint32_t& r0, uint32_t& r1, uint32_t& r2, uint32_t& r3,
                                        const void* p) {
    uint32_t a = (uint32_t)__cvta_generic_to_shared(p);
    asm volatile("ldmatrix.sync.aligned.m8n8.x4.shared.b16 {%0,%1,%2,%3}, [%4];"
                 : "=r"(r0), "=r"(r1), "=r"(r2), "=r"(r3) : "r"(a));
}

// fp16 single-pass GEMM: acc[2][4][4] += A(32x128, pitch HP_) @ W^T (128x128, pitch HP_)
__device__ __forceinline__ void run_f16(float (&acc)[2][4][4],
    const __half* __restrict__ A, const __half* __restrict__ W, int lane, int wc)
{
    const int rl = lane & 15;
    const int kp = (lane >> 4) << 3;
#pragma unroll
    for (int ks = 0; ks < 8; ks++) {
        const int k0 = ks*16 + kp;
        uint32_t a[2][4];
#pragma unroll
        for (int mt = 0; mt < 2; mt++)
            ldsm_x4(a[mt][0], a[mt][1], a[mt][2], a[mt][3], A + (mt*16 + rl)*HP_ + k0);
#pragma unroll
        for (int np = 0; np < 2; np++) {
            uint32_t b[4];
            ldsm_x4(b[0], b[1], b[2], b[3], W + (wc*32 + np*16 + rl)*HP_ + k0);
#pragma unroll
            for (int mt = 0; mt < 2; mt++) {
                mma_f16(acc[mt][np*2+0], a[mt][0], a[mt][1], a[mt][2], a[mt][3], b[0], b[2]);
                mma_f16(acc[mt][np*2+1], a[mt][0], a[mt][1], a[mt][2], a[mt][3], b[1], b[3]);
            }
        }
    }
}

__device__ __forceinline__ void cpa16(uint32_t d, const void* s) {
    asm volatile("cp.async.cg.shared.global [%0], [%1], 16;\n" :: "r"(d), "l"(s));
}
__device__ __forceinline__ void stage1(uint32_t dstB, const __half* __restrict__ src, int tid)
{
#pragma unroll
    for (int it = 0; it < 8; it++) {
        int i = tid + it*NT_;
        int row = i >> 4, seg = (i & 15) << 3;
        cpa16(dstB + (uint32_t)(row*HP_ + seg)*2u, src + row*128 + seg);
    }
}
__device__ __forceinline__ void cp_wait_all() {
    asm volatile("cp.async.commit_group;\n");
    asm volatile("cp.async.wait_group 0;\n" ::: "memory");
}

// gi loaders
__device__ __forceinline__ void load_gi1(float (&acc)[2][4][4], int jg, int t,
    const unsigned* __restrict__ sh_k, const float* __restrict__ sh_bh, int addbias,
    int rbase, int g, int tg2, int wc)
{
#pragma unroll
    for (int mt = 0; mt < 2; mt++) {
        int u0 = (int)((sh_k[rbase + mt*16 + g]     >> (4*t)) & 7u);
        int u1 = (int)((sh_k[rbase + mt*16 + g + 8] >> (4*t)) & 7u);
#pragma unroll
        for (int nt = 0; nt < 4; nt++) {
            int cc = jg*F_ + wc*32 + nt*8 + tg2;
            float2 p0 = *(const float2*)&g_wg[u0*G3_ + cc];
            float2 p1 = *(const float2*)&g_wg[u1*G3_ + cc];
            acc[mt][nt][0]=p0.x; acc[mt][nt][1]=p0.y; acc[mt][nt][2]=p1.x; acc[mt][nt][3]=p1.y;
            if (addbias) {
                float2 bh = *(const float2*)&sh_bh[cc];
                acc[mt][nt][0]+=bh.x; acc[mt][nt][1]+=bh.y; acc[mt][nt][2]+=bh.x; acc[mt][nt][3]+=bh.y;
            }
        }
    }
}
// gi2 = P[node] + GX[t][pid] (+bias)
__device__ __forceinline__ void load_gi2(float (&acc)[2][4][4], int jg, int t,
    const int* __restrict__ sh_i, const int* __restrict__ sh_pid,
    const float* __restrict__ sh_bh, int addbias,
    int rbase, int g, int tg2, int wc)
{
#pragma unroll
    for (int mt = 0; mt < 2; mt++) {
        int r0 = rbase + mt*16 + g, r1 = r0 + 8;
        int i0 = sh_i[r0], i1 = sh_i[r1];
        const float* gx0 = &g_GX[((size_t)t*TAB_ + sh_pid[r0])*G3_];
        const float* gx1 = &g_GX[((size_t)t*TAB_ + sh_pid[r1])*G3_];
#pragma unroll
        for (int nt = 0; nt < 4; nt++) {
            int cc = jg*F_ + wc*32 + nt*8 + tg2;
            float2 p0 = *(const float2*)&g_P[(size_t)i0*G3_ + cc];
            float2 p1 = *(const float2*)&g_P[(size_t)i1*G3_ + cc];
            float2 q0 = *(const float2*)&gx0[cc];
            float2 q1 = *(const float2*)&gx1[cc];
            acc[mt][nt][0]=p0.x+q0.x; acc[mt][nt][1]=p0.y+q0.y;
            acc[mt][nt][2]=p1.x+q1.x; acc[mt][nt][3]=p1.y+q1.y;
            if (addbias) {
                float2 bh = *(const float2*)&sh_bh[cc];
                acc[mt][nt][0]+=bh.x; acc[mt][nt][1]+=bh.y; acc[mt][nt][2]+=bh.x; acc[mt][nt][3]+=bh.y;
            }
        }
    }
}

// ---------------- preprocessing ----------------
__global__ void prep_kernel(const int* __restrict__ walks)
{
    int m = blockIdx.x * blockDim.x + threadIdx.x;
    if (m >= SEQ_) return;
    int w[L_];
#pragma unroll
    for (int p = 0; p < L_; p++) w[p] = walks[m*L_ + p];
    unsigned pk = 0;
#pragma unroll
    for (int t = 0; t < L_; t++) {
        int p = L_-1-t, wp = w[p], u = p;
#pragma unroll
        for (int q = L_-1; q >= 0; q--) if (w[q] == wp) u = q;
        g_walksf[m*L_ + t] = wp;
        pk |= ((unsigned)u) << (4*t);
    }
    g_upk[m] = pk;
    g_need[m] = 0;
}

__global__ void tabinit_kernel()
{
    int i = blockIdx.x*256 + threadIdx.x;
    if (i < TAB_) g_tabkey[i] = KINV;
}

__global__ void dedup_kernel()
{
    int m = blockIdx.x*256 + threadIdx.x;
    if (m >= SEQ_) return;
    unsigned key = g_upk[m];
    unsigned hx = (key * 2654435761u) >> 19;
    for (;;) {
        unsigned prev = atomicCAS(&g_tabkey[hx], KINV, key);
        if (prev == KINV || prev == key) { g_pid[m] = (int)hx; break; }
        hx = (hx + 1) & (TAB_ - 1);
    }
}

__global__ void flag_kernel(const int* __restrict__ idxs)
{
    int i = threadIdx.x + blockIdx.x*128;
    if (i >= S_*SUB_) return;
    int s = i / SUB_, j = i % SUB_;
    g_need[s*N_ + idxs[j]] = 1;
}

__global__ void wg_kernel(const float* __restrict__ Wih_w, const float* __restrict__ bih_w)
{
    int j = threadIdx.x;
    float b = bih_w[j];
#pragma unroll
    for (int u = 0; u < 8; u++) g_wg[u*G3_ + j] = Wih_w[j*8 + u] + b;
}

__global__ void pack_kernel(const float* __restrict__ Whh_w, const float* __restrict__ Whh,
                            const float* __restrict__ Wih)
{
    int i = blockIdx.x * 256 + threadIdx.x;
    if (i >= G3_*F_) return;
    g_W1[i] = __float2half(Whh_w[i]);
    g_W2[i] = __float2half(Whh[i]);
    int n = i >> 7, k = i & 127;
    g_WX[i] = __float2half(Wih[n*256 + 128 + k]);
    g_WA[i] = __float2half(Wih[n*256 + k]);
}

__global__ void packh_kernel(const float* __restrict__ h)
{
    int i = blockIdx.x * 256 + threadIdx.x;
    if (i >= NP_*F_) return;
    int n = i >> 7, k = i & 127;
    float v = (n < N_) ? h[(size_t)n*F_ + k] : 0.f;
    g_hH[(size_t)n*F_ + k] = __float2half(v);
}

// ---------------- P = h @ WihA^T + bih ----------------
__global__ void __launch_bounds__(NT_) pT_kernel(const float* __restrict__ bih)
{
    extern __shared__ char smc[];
    __half* sh_x = (__half*)smc;
    __half* sh_W = (__half*)(smc + 17408);

    const int tid = threadIdx.x, wid = tid >> 5, lane = tid & 31;
    const int wr = wid & 1, wc = wid >> 1;
    const int g = lane >> 2, tg2 = (lane & 3)*2;
    const int rbase = wr*32;
    const int m0 = blockIdx.x*MB_, jg = blockIdx.y;
    const uint32_t sWu = (uint32_t)__cvta_generic_to_shared(sh_W);

#pragma unroll
    for (int it = 0; it < 4; it++) {
        int i = tid + it*NT_;
        int row = i >> 4, seg = (i & 15) << 3;
        *(uint4*)(sh_x + row*HP_ + seg) = *(const uint4*)(g_hH + (size_t)(m0 + row)*F_ + seg);
    }
    stage1(sWu, g_WA + (size_t)jg*16384, tid);
    cp_wait_all();
    __syncthreads();

    float acc[2][4][4];
#pragma unroll
    for (int mt = 0; mt < 2; mt++)
#pragma unroll
        for (int nt = 0; nt < 4; nt++) {
            int cc = jg*F_ + wc*32 + nt*8 + tg2;
            float2 b = *(const float2*)&bih[cc];
            acc[mt][nt][0]=b.x; acc[mt][nt][1]=b.y; acc[mt][nt][2]=b.x; acc[mt][nt][3]=b.y;
        }
    run_f16(acc, sh_x + rbase*HP_, sh_W, lane, wc);

#pragma unroll
    for (int mt = 0; mt < 2; mt++)
#pragma unroll
        for (int nt = 0; nt < 4; nt++) {
            int cc = jg*F_ + wc*32 + nt*8 + tg2;
#pragma unroll
            for (int p2 = 0; p2 < 2; p2++) {
                int n = m0 + rbase + mt*16 + g + p2*8;
                if (n < N_)
                    *(float2*)&g_P[(size_t)n*G3_ + cc] =
                        make_float2(acc[mt][nt][p2*2], acc[mt][nt][p2*2+1]);
            }
        }
}

// ---------------- GRU1 over dedup table slots ----------------
__global__ void __launch_bounds__(NT_, 2) gru1_kernel(const float* __restrict__ bhh)
{
    extern __shared__ char smc[];
    float*  sh_hf = (float*)smc;                         // 33792
    __half* sh_ha = (__half*)(smc + 33792);              // 17408
    __half* sh_W  = (__half*)(smc + 33792 + 17408);      // 34816
    float*  sh_bh = (float*)(smc + 33792 + 17408 + 34816);
    unsigned* sh_k = (unsigned*)(smc + 33792 + 17408 + 34816 + 1536);

    const int tid = threadIdx.x, wid = tid >> 5, lane = tid & 31;
    const int wr = wid & 1, wc = wid >> 1;
    const int g = lane >> 2, tg2 = (lane & 3)*2;
    const int rbase = wr*32;
    const int m0 = blockIdx.x*MB_;
    const uint32_t sWu = (uint32_t)__cvta_generic_to_shared(sh_W);

    if (tid < MB_) sh_k[tid] = g_tabkey[m0 + tid];
    __syncthreads();
    {
        int any = 0;
        if (tid < MB_ && sh_k[tid] != KINV) any = 1;
        if (!__syncthreads_or(any)) return;
    }
    for (int i = tid; i < G3_; i += NT_) sh_bh[i] = bhh[i];
    for (int i = tid; i < MB_*FP_; i += NT_) sh_hf[i] = 0.f;
    for (int i = tid; i < MB_*HP_/2; i += NT_) ((uint32_t*)sh_ha)[i] = 0u;

#pragma unroll 1
    for (int t = 0; t < L_; t++) {
        const bool doH = (t > 0);
        float nn[2][4][4];
        {
            float rr[2][4][4];
            __syncthreads();
            if (doH) { stage1(sWu, g_W1, tid); cp_wait_all(); }
            __syncthreads();
            load_gi1(rr, 0, t, sh_k, sh_bh, 1, rbase, g, tg2, wc);
            if (doH) run_f16(rr, sh_ha + rbase*HP_, sh_W, lane, wc);
#pragma unroll
            for (int mt=0; mt<2; mt++)
#pragma unroll
                for (int nt=0; nt<4; nt++)
#pragma unroll
                    for (int q=0; q<4; q++) rr[mt][nt][q] = sigf(rr[mt][nt][q]);

            __syncthreads();
            if (doH) { stage1(sWu, g_W1 + 2*16384, tid); cp_wait_all(); }
            __syncthreads();
            float acci[2][4][4], acch[2][4][4];
            load_gi1(acci, 2, t, sh_k, nullptr, 0, rbase, g, tg2, wc);
#pragma unroll
            for (int mt=0; mt<2; mt++)
#pragma unroll
                for (int nt=0; nt<4; nt++) {
                    int cc = 2*F_ + wc*32 + nt*8 + tg2;
                    float2 bh = *(const float2*)&sh_bh[cc];
                    acch[mt][nt][0]=bh.x; acch[mt][nt][1]=bh.y;
                    acch[mt][nt][2]=bh.x; acch[mt][nt][3]=bh.y;
                }
            if (doH) run_f16(acch, sh_ha + rbase*HP_, sh_W, lane, wc);
#pragma unroll
            for (int mt=0; mt<2; mt++)
#pragma unroll
                for (int nt=0; nt<4; nt++)
#pragma unroll
                    for (int q=0; q<4; q++)
                        nn[mt][nt][q] = tanh_s(acci[mt][nt][q] + rr[mt][nt][q]*acch[mt][nt][q]);
        }

        float zz[2][4][4];
        __syncthreads();
        if (doH) { stage1(sWu, g_W1 + 1*16384, tid); cp_wait_all(); }
        __syncthreads();
        load_gi1(zz, 1, t, sh_k, sh_bh, 1, rbase, g, tg2, wc);
        if (doH) run_f16(zz, sh_ha + rbase*HP_, sh_W, lane, wc);
#pragma unroll
        for (int mt=0; mt<2; mt++)
#pragma unroll
            for (int nt=0; nt<4; nt++)
#pragma unroll
                for (int q=0; q<4; q++) zz[mt][nt][q] = sigf(zz[mt][nt][q]);

        __syncthreads();
#pragma unroll
        for (int mt=0; mt<2; mt++)
#pragma unroll
            for (int nt=0; nt<4; nt++) {
                int cc = wc*32 + nt*8 + tg2;
#pragma unroll
                for (int p2=0; p2<2; p2++) {
                    int r = rbase + mt*16 + g + p2*8;
                    float n0 = nn[mt][nt][p2*2], n1 = nn[mt][nt][p2*2+1];
                    float z0 = zz[mt][nt][p2*2], z1 = zz[mt][nt][p2*2+1];
                    float2 ho = *(const float2*)&sh_hf[r*FP_ + cc];
                    float h0 = (1.f - z0)*n0 + z0*ho.x;
                    float h1 = (1.f - z1)*n1 + z1*ho.y;
                    *(float2*)&sh_hf[r*FP_ + cc] = make_float2(h0, h1);
                    __half2 hv = __floats2half2_rn(h0, h1);
                    *(__half2*)&sh_ha[r*HP_ + cc] = hv;
                    *(__half2*)&g_ywH[((size_t)t*TAB_ + m0 + r)*F_ + cc] = hv;
                }
            }
    }
}

// ---------------- GX = y_walk @ WX^T over dedup slots ----------------
__global__ void __launch_bounds__(NT_, 2) gx_kernel()
{
    extern __shared__ char smc[];
    __half* sh_x = (__half*)smc;                         // 17408
    __half* sh_W = (__half*)(smc + 17408);               // 34816
    unsigned* sh_k = (unsigned*)(smc + 17408 + 34816);   // 256

    const int tid = threadIdx.x, wid = tid >> 5, lane = tid & 31;
    const int wr = wid & 1, wc = wid >> 1;
    const int g = lane >> 2, tg2 = (lane & 3)*2;
    const int rbase = wr*32;
    const int m0 = blockIdx.x*MB_;
    const int t  = blockIdx.y;
    const uint32_t sWu = (uint32_t)__cvta_generic_to_shared(sh_W);

    if (tid < MB_) sh_k[tid] = g_tabkey[m0 + tid];
    __syncthreads();
    {
        int any = 0;
        if (tid < MB_ && sh_k[tid] != KINV) any = 1;
        if (!__syncthreads_or(any)) return;
    }
#pragma unroll
    for (int it = 0; it < 4; it++) {
        int i = tid + it*NT_;
        int row = i >> 4, seg = (i & 15) << 3;
        *(uint4*)(sh_x + row*HP_ + seg) =
            *(const uint4*)(g_ywH + ((size_t)t*TAB_ + m0 + row)*F_ + seg);
    }

#pragma unroll 1
    for (int jg = 0; jg < 3; jg++) {
        __syncthreads();      // x visible (jg=0) / prior run's sh_W reads done
        stage1(sWu, g_WX + (size_t)jg*16384, tid);
        cp_wait_all();
        __syncthreads();
        float acc[2][4][4];
#pragma unroll
        for (int mt=0; mt<2; mt++)
#pragma unroll
            for (int nt=0; nt<4; nt++)
#pragma unroll
                for (int q=0; q<4; q++) acc[mt][nt][q] = 0.f;
        run_f16(acc, sh_x + rbase*HP_, sh_W, lane, wc);
#pragma unroll
        for (int mt=0; mt<2; mt++)
#pragma unroll
            for (int nt=0; nt<4; nt++) {
                int cc = jg*F_ + wc*32 + nt*8 + tg2;
#pragma unroll
                for (int p2=0; p2<2; p2++) {
                    int r = rbase + mt*16 + g + p2*8;
                    *(float2*)&g_GX[((size_t)t*TAB_ + m0 + r)*G3_ + cc] =
                        make_float2(acc[mt][nt][p2*2], acc[mt][nt][p2*2+1]);
                }
            }
    }
}

// ---------------- GRU2: h-GEMM only (gi fully gathered) ----------------
__global__ void __launch_bounds__(NT_, 2) gru2_kernel(const float* __restrict__ bhh,
                                                      float* __restrict__ hT_out)
{
    extern __shared__ char smc[];
    float*  sh_hf = (float*)smc;                         // 33792
    __half* sh_ha = (__half*)(smc + 33792);              // 17408
    __half* sh_W  = (__half*)(smc + 51200);              // 34816
    float*  sh_bh = (float*)(smc + 86016);               // 1536
    int*    sh_i  = (int*)(smc + 87552);                 // 256
    int*    sh_pid = (int*)(smc + 87808);                // 256

    const int tid = threadIdx.x, wid = tid >> 5, lane = tid & 31;
    const int wr = wid & 1, wc = wid >> 1;
    const int g = lane >> 2, tg2 = (lane & 3)*2;
    const int rbase = wr*32;
    const int m0 = blockIdx.x*MB_;
    const uint32_t sWu = (uint32_t)__cvta_generic_to_shared(sh_W);

    for (int i = tid; i < G3_; i += NT_) sh_bh[i] = bhh[i];
    if (tid < MB_) sh_pid[tid] = g_pid[m0 + tid];
    __syncthreads();
    for (int i = tid; i < MB_*F_; i += NT_) {
        int row = i >> 7, k = i & 127;
        __half v = g_ywH[((size_t)(L_-1)*TAB_ + sh_pid[row])*F_ + k];
        sh_ha[row*HP_ + k] = v;
        sh_hf[row*FP_ + k] = __half2float(v);
    }

#pragma unroll 1
    for (int t = 0; t < L_; t++) {
        __syncthreads();   // epilogue writes of sh_ha done; prior sh_W reads done
        if (tid < MB_) sh_i[tid] = g_walksf[(size_t)(m0 + tid)*L_ + t];
        __syncthreads();   // sh_i visible

        float nn[2][4][4];
        {
            // gate r
            float rr[2][4][4];
            load_gi2(rr, 0, t, sh_i, sh_pid, sh_bh, 1, rbase, g, tg2, wc);
            stage1(sWu, g_W2, tid);
            cp_wait_all(); __syncthreads();
            run_f16(rr, sh_ha + rbase*HP_, sh_W, lane, wc);
#pragma unroll
            for (int mt=0; mt<2; mt++)
#pragma unroll
                for (int nt=0; nt<4; nt++)
#pragma unroll
                    for (int q=0; q<4; q++) rr[mt][nt][q] = sigf(rr[mt][nt][q]);

            // gate n
            __syncthreads();   // rr run done, sh_W free
            float acci[2][4][4], acch[2][4][4];
            load_gi2(acci, 2, t, sh_i, sh_pid, nullptr, 0, rbase, g, tg2, wc);
#pragma unroll
            for (int mt=0; mt<2; mt++)
#pragma unroll
                for (int nt=0; nt<4; nt++) {
                    int cc = 2*F_ + wc*32 + nt*8 + tg2;
                    float2 bh = *(const float2*)&sh_bh[cc];
                    acch[mt][nt][0]=bh.x; acch[mt][nt][1]=bh.y;
                    acch[mt][nt][2]=bh.x; acch[mt][nt][3]=bh.y;
                }
            stage1(sWu, g_W2 + 2*16384, tid);
            cp_wait_all(); __syncthreads();
            run_f16(acch, sh_ha + rbase*HP_, sh_W, lane, wc);
#pragma unroll
            for (int mt=0; mt<2; mt++)
#pragma unroll
                for (int nt=0; nt<4; nt++)
#pragma unroll
                    for (int q=0; q<4; q++)
                        nn[mt][nt][q] = tanh_s(acci[mt][nt][q] + rr[mt][nt][q]*acch[mt][nt][q]);
        }

        // gate z
        float zz[2][4][4];
        __syncthreads();
        load_gi2(zz, 1, t, sh_i, sh_pid, sh_bh, 1, rbase, g, tg2, wc);
        stage1(sWu, g_W2 + 1*16384, tid);
        cp_wait_all(); __syncthreads();
        run_f16(zz, sh_ha + rbase*HP_, sh_W, lane, wc);
#pragma unroll
        for (int mt=0; mt<2; mt++)
#pragma unroll
            for (int nt=0; nt<4; nt++)
#pragma unroll
                for (int q=0; q<4; q++) zz[mt][nt][q] = sigf(zz[mt][nt][q]);

        __syncthreads();   // all ha reads complete
#pragma unroll
        for (int mt=0; mt<2; mt++)
#pragma unroll
            for (int nt=0; nt<4; nt++) {
                int cc = wc*32 + nt*8 + tg2;
#pragma unroll
                for (int p2=0; p2<2; p2++) {
                    int r = rbase + mt*16 + g + p2*8;
                    float n0 = nn[mt][nt][p2*2], n1 = nn[mt][nt][p2*2+1];
                    float z0 = zz[mt][nt][p2*2], z1 = zz[mt][nt][p2*2+1];
                    float2 ho = *(const float2*)&sh_hf[r*FP_ + cc];
                    float h0 = (1.f - z0)*n0 + z0*ho.x;
                    float h1 = (1.f - z1)*n1 + z1*ho.y;
                    *(float2*)&sh_hf[r*FP_ + cc] = make_float2(h0, h1);
                    *(__half2*)&sh_ha[r*HP_ + cc] = __floats2half2_rn(h0, h1);
                    if (t < L_-1) {
                        if (g_need[m0 + r])
                            *(float2*)&g_yseq[t][((size_t)(m0+r))*F_ + cc] = make_float2(h0, h1);
                    } else {
                        *(float2*)&hT_out[((size_t)(m0+r))*F_ + cc] = make_float2(h0, h1);
                    }
                }
            }
    }
}

// ---------------- loss ----------------
__global__ void lsum_kernel(const int* __restrict__ idxs, const float* __restrict__ y0)
{
    int b = blockIdx.x;
    int t = b % (L_-1), j = (b/(L_-1)) % SUB_, s = b/((L_-1)*SUB_);
    int seq = s*N_ + idxs[j];
    int node = g_walksf[(size_t)seq*L_ + t + 1];
    int o = threadIdx.x;
    __shared__ float red[OR_];
    red[o] = y0[(size_t)node*OR_ + o]; __syncthreads();
    for (int st = OR_/2; st > 0; st >>= 1) { if (o < st) red[o] += red[o+st]; __syncthreads(); }
    if (o == 0) g_part1[b] = red[0];
}

__global__ void lred1_kernel()
{
    __shared__ float red[256];
    int tid = threadIdx.x; float s = 0.f;
    for (int i = tid; i < NB_LOSS; i += 256) s += g_part1[i];
    red[tid] = s; __syncthreads();
    for (int st = 128; st > 0; st >>= 1) { if (tid < st) red[tid] += red[tid+st]; __syncthreads(); }
    if (tid == 0) g_posw = LOSS_CNT / red[0];
}

__global__ void lbce_kernel(const int* __restrict__ idxs, const float* __restrict__ y0,
                            const float* __restrict__ Wss, const float* __restrict__ bss)
{
    int b = blockIdx.x;
    int t = b % (L_-1), j = (b/(L_-1)) % SUB_, s = b/((L_-1)*SUB_);
    int seq = s*N_ + idxs[j];
    __shared__ float yrow[F_];
    int o = threadIdx.x;
    yrow[o]      = g_yseq[t][(size_t)seq*F_ + o];
    yrow[o + 64] = g_yseq[t][(size_t)seq*F_ + o + 64];
    __syncthreads();
    float acc = bss[o];
    const float4* wrp = (const float4*)(Wss + (size_t)o*F_);
#pragma unroll 8
    for (int k = 0; k < F_/4; k++) {
        float4 w = wrp[k];
        acc += yrow[k*4]*w.x + yrow[k*4+1]*w.y + yrow[k*4+2]*w.z + yrow[k*4+3]*w.w;
    }
    int node = g_walksf[(size_t)seq*L_ + t + 1];
    float yt = y0[(size_t)node*OR_ + o];
    float term = g_posw * yt * softplusf(-acc) + (1.f - yt) * softplusf(acc);
    __shared__ float red[OR_];
    red[o] = term; __syncthreads();
    for (int st = OR_/2; st > 0; st >>= 1) { if (o < st) red[o] += red[o+st]; __syncthreads(); }
    if (o == 0) g_part2[b] = red[0];
}

__global__ void lred2_kernel(float* __restrict__ dst)
{
    __shared__ float red[256];
    int tid = threadIdx.x; float s = 0.f;
    for (int i = tid; i < NB_LOSS; i += 256) s += g_part2[i];
    red[tid] = s; __syncthreads();
    for (int st = 128; st > 0; st >>= 1) { if (tid < st) red[tid] += red[tid+st]; __syncthreads(); }
    if (tid == 0) *dst = red[0] / LOSS_CNT;
}

// ---------------- launch ----------------
extern "C" void kernel_launch(void* const* d_in, const int* in_sizes, int n_in,
                              void* d_out, int out_size)
{
    const float* h     = (const float*)d_in[0];
    const float* y0    = (const float*)d_in[1];
    const float* Wih_w = (const float*)d_in[2];
    const float* Whh_w = (const float*)d_in[3];
    const float* bih_w = (const float*)d_in[4];
    const float* bhh_w = (const float*)d_in[5];
    const float* Wih   = (const float*)d_in[6];
    const float* Whh   = (const float*)d_in[7];
    const float* bih   = (const float*)d_in[8];
    const float* bhh   = (const float*)d_in[9];
    const float* W_ss  = (const float*)d_in[10];
    const float* b_ss  = (const float*)d_in[11];
    const int*   walks = (const int*)d_in[12];
    const int*   idxs  = (const int*)d_in[13];
    float* out = (float*)d_out;

    const int SMEM_PT = 17408 + 34816;                               // 52224
    const int SMEM_G1 = 33792 + 17408 + 34816 + 1536 + 256;          // 87808
    const int SMEM_GX = 17408 + 34816 + 256;                         // 52480
    const int SMEM_G2 = 33792 + 17408 + 34816 + 1536 + 256 + 256;    // 88064
    cudaFuncSetAttribute(pT_kernel,   cudaFuncAttributeMaxDynamicSharedMemorySize, SMEM_PT);
    cudaFuncSetAttribute(gru1_kernel, cudaFuncAttributeMaxDynamicSharedMemorySize, SMEM_G1);
    cudaFuncSetAttribute(gx_kernel,   cudaFuncAttributeMaxDynamicSharedMemorySize, SMEM_GX);
    cudaFuncSetAttribute(gru2_kernel, cudaFuncAttributeMaxDynamicSharedMemorySize, SMEM_G2);

    prep_kernel<<<(SEQ_ + 255)/256, 256>>>(walks);
    tabinit_kernel<<<(TAB_ + 255)/256, 256>>>();
    dedup_kernel<<<(SEQ_ + 255)/256, 256>>>();
    flag_kernel<<<(S_*SUB_ + 127)/128, 128>>>(idxs);
    wg_kernel<<<1, G3_>>>(Wih_w, bih_w);
    pack_kernel<<<(G3_*F_ + 255)/256, 256>>>(Whh_w, Whh, Wih);
    packh_kernel<<<(NP_*F_ + 255)/256, 256>>>(h);
    pT_kernel<<<dim3(PTILES_, 3), NT_, SMEM_PT>>>(bih);
    gru1_kernel<<<TTILES_, NT_, SMEM_G1>>>(bhh_w);
    gx_kernel<<<dim3(TTILES_, L_), NT_, SMEM_GX>>>();
    gru2_kernel<<<TILES_, NT_, SMEM_G2>>>(bhh, out);
    lsum_kernel<<<NB_LOSS, OR_>>>(idxs, y0);
    lred1_kernel<<<1, 256>>>();
    lbce_kernel<<<NB_LOSS, OR_>>>(idxs, y0, W_ss, b_ss);
    lred2_kernel<<<1, 256>>>(out + (out_size - 1));
}